// round 6
// baseline (speedup 1.0000x reference)
#include <cuda_runtime.h>
#include <cuda_bf16.h>
#include <cstdint>

#define B_   64
#define NN_  64
#define HL_  50
#define IN_  384
#define POS_ 64
#define ATT_ 256
#define NEWS_ 448
#define W1COLS_ 896

// Scratch
__device__ float g_pn[B_ * NN_ * ATT_];
__device__ float g_pl[B_ * HL_ * ATT_];
__device__ float g_cn[ATT_];
__device__ float g_cl[HL_ * ATT_];
__device__ float g_attn[B_ * NN_ * 52];
__device__ int   g_act[B_ * 52];
__device__ int   g_cntflag[B_];          // cnt | (unif<<8)

__device__ __forceinline__ float tanh_fast(float x) {
    float y; asm("tanh.approx.f32 %0, %1;" : "=f"(y) : "f"(x)); return y;
}
__device__ __forceinline__ uint32_t to_tf32(float f) {
    uint32_t r; asm("cvt.rna.tf32.f32 %0, %1;" : "=r"(r) : "f"(f)); return r;
}
__device__ __forceinline__ void mma_tf32(float* c, const uint32_t* a, const uint32_t* b) {
    asm volatile(
        "mma.sync.aligned.m16n8k8.row.col.f32.tf32.tf32.f32 "
        "{%0,%1,%2,%3}, {%4,%5,%6,%7}, {%8,%9}, {%0,%1,%2,%3};"
        : "+f"(c[0]), "+f"(c[1]), "+f"(c[2]), "+f"(c[3])
        : "r"(a[0]), "r"(a[1]), "r"(a[2]), "r"(a[3]), "r"(b[0]), "r"(b[1]));
}

// ---------------------------------------------------------------------------
// Kernel A: cn / cl bias folding + per-b mask compaction
// ---------------------------------------------------------------------------
__global__ __launch_bounds__(256) void cncl_kernel(
    const float* __restrict__ pos_emb,
    const float* __restrict__ W1,
    const float* __restrict__ b1,
    const int*   __restrict__ log_mask)
{
    int a = threadIdx.x;
    int blk = blockIdx.x;
    if (blk == 0) {
        float s = b1[a];
        const float* w = W1 + a * W1COLS_ + IN_;
        #pragma unroll 8
        for (int p = 0; p < POS_; p++) s += pos_emb[p] * w[p];
        g_cn[a] = s;
    } else if (blk <= HL_) {
        int h = blk - 1;
        float s = 0.f;
        const float* w  = W1 + a * W1COLS_ + NEWS_ + IN_;
        const float* pe = pos_emb + (1 + h) * POS_;
        #pragma unroll 8
        for (int p = 0; p < POS_; p++) s += pe[p] * w[p];
        g_cl[h * ATT_ + a] = s;
    } else {
        int b = a;
        if (b < B_) {
            int c = 0;
            int buf[HL_];
            #pragma unroll
            for (int h = 0; h < HL_; h++)
                if (log_mask[b * HL_ + h] != 0) buf[c++] = h;
            int unif = (c == 0);
            if (unif) { for (int h = 0; h < HL_; h++) buf[h] = h; c = HL_; }
            for (int j = 0; j < c; j++) g_act[b * 52 + j] = buf[j];
            g_cntflag[b] = c | (unif << 8);
        }
    }
}

// ---------------------------------------------------------------------------
// Kernel B: mma.sync tf32 GEMM (unchanged)
// ---------------------------------------------------------------------------
#define BK 32
#define LDT 36
#define NKT (IN_ / BK)

__global__ __launch_bounds__(256) void gemm_mma_kernel(
    const float* __restrict__ news_vec,
    const float* __restrict__ log_vec,
    const float* __restrict__ W1)
{
    __shared__ uint32_t As[128 * LDT];
    __shared__ uint32_t Ws[128 * LDT];

    int tid  = threadIdx.x;
    int wid  = tid >> 5, lane = tid & 31;
    int gid  = lane >> 2, tig = lane & 3;
    int wm   = wid & 1;
    int wn   = wid >> 1;

    int bx   = blockIdx.x;
    int nh   = bx & 1;
    int tile = bx >> 1;
    int mode, mtile, w_off;
    const float* A;
    if (tile < 32) { mode = 0; mtile = tile;      A = news_vec; w_off = 0; }
    else           { mode = 1; mtile = tile - 32; A = log_vec;  w_off = NEWS_; }
    int n_base = nh * 128;

    int lrow = tid >> 3;
    int lf4  = tid & 7;
    const float* Abase = A  + (size_t)(mtile * 128 + lrow) * IN_ + lf4 * 4;
    const float* Wbase = W1 + (size_t)(n_base + lrow) * W1COLS_ + w_off + lf4 * 4;

    float acc[4][4][4];
    #pragma unroll
    for (int i = 0; i < 4; i++)
        #pragma unroll
        for (int j = 0; j < 4; j++)
            #pragma unroll
            for (int k = 0; k < 4; k++) acc[i][j][k] = 0.f;

    float4 aReg[4], wReg[4];
    #pragma unroll
    for (int p = 0; p < 4; p++) {
        aReg[p] = *(const float4*)(Abase + (size_t)p * 32 * IN_);
        wReg[p] = *(const float4*)(Wbase + (size_t)p * 32 * W1COLS_);
    }

    for (int kt = 0; kt < NKT; kt++) {
        #pragma unroll
        for (int p = 0; p < 4; p++) {
            uint32_t* as = &As[(p * 32 + lrow) * LDT + lf4 * 4];
            as[0] = to_tf32(aReg[p].x); as[1] = to_tf32(aReg[p].y);
            as[2] = to_tf32(aReg[p].z); as[3] = to_tf32(aReg[p].w);
            uint32_t* ws = &Ws[(p * 32 + lrow) * LDT + lf4 * 4];
            ws[0] = to_tf32(wReg[p].x); ws[1] = to_tf32(wReg[p].y);
            ws[2] = to_tf32(wReg[p].z); ws[3] = to_tf32(wReg[p].w);
        }
        __syncthreads();

        if (kt + 1 < NKT) {
            const float* An = Abase + (kt + 1) * BK;
            const float* Wn = Wbase + (kt + 1) * BK;
            #pragma unroll
            for (int p = 0; p < 4; p++) {
                aReg[p] = *(const float4*)(An + (size_t)p * 32 * IN_);
                wReg[p] = *(const float4*)(Wn + (size_t)p * 32 * W1COLS_);
            }
        }

        #pragma unroll
        for (int kk = 0; kk < BK; kk += 8) {
            uint32_t afr[4][4], bfr[4][2];
            #pragma unroll
            for (int mf = 0; mf < 4; mf++) {
                int r0 = (wm * 64 + mf * 16 + gid) * LDT + kk + tig;
                afr[mf][0] = As[r0];
                afr[mf][1] = As[r0 + 8 * LDT];
                afr[mf][2] = As[r0 + 4];
                afr[mf][3] = As[r0 + 8 * LDT + 4];
            }
            #pragma unroll
            for (int nf = 0; nf < 4; nf++) {
                int c0 = (wn * 32 + nf * 8 + gid) * LDT + kk + tig;
                bfr[nf][0] = Ws[c0];
                bfr[nf][1] = Ws[c0 + 4];
            }
            #pragma unroll
            for (int mf = 0; mf < 4; mf++)
                #pragma unroll
                for (int nf = 0; nf < 4; nf++)
                    mma_tf32(acc[mf][nf], afr[mf], bfr[nf]);
        }
        __syncthreads();
    }

    float* outp = (mode == 0) ? g_pn : g_pl;
    #pragma unroll
    for (int mf = 0; mf < 4; mf++) {
        int r0 = mtile * 128 + wm * 64 + mf * 16 + gid;
        int r1 = r0 + 8;
        const float* bias0;
        const float* bias1;
        if (mode == 0) { bias0 = g_cn; bias1 = g_cn; }
        else { bias0 = g_cl + (r0 % HL_) * ATT_; bias1 = g_cl + (r1 % HL_) * ATT_; }
        #pragma unroll
        for (int nf = 0; nf < 4; nf++) {
            int c = n_base + wn * 32 + nf * 8 + 2 * tig;
            float2 v0, v1;
            v0.x = acc[mf][nf][0] + bias0[c];
            v0.y = acc[mf][nf][1] + bias0[c + 1];
            v1.x = acc[mf][nf][2] + bias1[c];
            v1.y = acc[mf][nf][3] + bias1[c + 1];
            *(float2*)(outp + (size_t)r0 * ATT_ + c) = v0;
            *(float2*)(outp + (size_t)r1 * ATT_ + c) = v1;
        }
    }
}

// ---------------------------------------------------------------------------
// Kernel C: attn. Block = (b, quarter) -> 16 n's; 8 warps, 2 n per warp,
// 2 j per inner step (4 independent accumulator chains, interleaved shfl).
// ---------------------------------------------------------------------------
#define ATTN_SMEM ((50 * 256 + 64) * 4)
__global__ __launch_bounds__(256, 2) void attn_kernel(
    const float* __restrict__ W2,
    const float* __restrict__ b2)
{
    extern __shared__ float sm[];
    float* pl_s  = sm;                 // 50*256
    int*   act_s = (int*)(sm + 12800); // 52

    int tid  = threadIdx.x;
    int b    = blockIdx.x >> 2;
    int q    = blockIdx.x & 3;
    int warp = tid >> 5, lane = tid & 31;

    int cf   = g_cntflag[b];
    int cnt  = cf & 0xff;
    int unif = cf >> 8;

    if (tid < 52) act_s[tid] = g_act[b * 52 + tid];
    __syncthreads();

    {
        int npl = cnt * 64;
        const float4* plg = (const float4*)(g_pl + (size_t)b * HL_ * ATT_);
        for (int i = tid; i < npl; i += 256) {
            int j = i >> 6, r = i & 63;
            ((float4*)pl_s)[j * 64 + r] = plg[(size_t)act_s[j] * 64 + r];
        }
    }
    float w2r[8];
    #pragma unroll
    for (int k = 0; k < 8; k++) w2r[k] = W2[lane + 32 * k];
    float bias2 = b2[0];
    __syncthreads();

    int n0 = q * 16 + warp;          // warp 0..7
    int n1 = n0 + 8;
    int bn0 = b * NN_ + n0;
    int bn1 = b * NN_ + n1;

    float pn0[8], pn1[8];
    #pragma unroll
    for (int k = 0; k < 8; k++) {
        pn0[k] = g_pn[(size_t)bn0 * ATT_ + lane + 32 * k];
        pn1[k] = g_pn[(size_t)bn1 * ATT_ + lane + 32 * k];
    }

    if (!unif) {
        // logits deposited per-lane: v0x = logit[lane] (j<32), v1x = logit[lane+32]
        float v0a = -3.0e38f, v1a = -3.0e38f;   // n0
        float v0b = -3.0e38f, v1b = -3.0e38f;   // n1
        int jj = 0;
        for (; jj + 1 < cnt; jj += 2) {
            const float* p0 = pl_s + jj * ATT_;
            const float* p1 = pl_s + (jj + 1) * ATT_;
            float s00 = 0.f, s01 = 0.f, s10 = 0.f, s11 = 0.f;
            #pragma unroll
            for (int k = 0; k < 8; k++) {
                float x0 = p0[lane + 32 * k];
                float x1 = p1[lane + 32 * k];
                s00 += tanh_fast(pn0[k] + x0) * w2r[k];
                s01 += tanh_fast(pn1[k] + x0) * w2r[k];
                s10 += tanh_fast(pn0[k] + x1) * w2r[k];
                s11 += tanh_fast(pn1[k] + x1) * w2r[k];
            }
            #pragma unroll
            for (int o = 16; o > 0; o >>= 1) {
                s00 += __shfl_xor_sync(0xffffffffu, s00, o);
                s01 += __shfl_xor_sync(0xffffffffu, s01, o);
                s10 += __shfl_xor_sync(0xffffffffu, s10, o);
                s11 += __shfl_xor_sync(0xffffffffu, s11, o);
            }
            if (jj < 32) {
                if (lane == jj) { v0a = s00 + bias2; v0b = s01 + bias2; }
            } else {
                if (lane == jj - 32) { v1a = s00 + bias2; v1b = s01 + bias2; }
            }
            int j2 = jj + 1;
            if (j2 < 32) {
                if (lane == j2) { v0a = s10 + bias2; v0b = s11 + bias2; }
            } else {
                if (lane == j2 - 32) { v1a = s10 + bias2; v1b = s11 + bias2; }
            }
        }
        if (jj < cnt) {
            const float* p0 = pl_s + jj * ATT_;
            float s00 = 0.f, s01 = 0.f;
            #pragma unroll
            for (int k = 0; k < 8; k++) {
                float x0 = p0[lane + 32 * k];
                s00 += tanh_fast(pn0[k] + x0) * w2r[k];
                s01 += tanh_fast(pn1[k] + x0) * w2r[k];
            }
            #pragma unroll
            for (int o = 16; o > 0; o >>= 1) {
                s00 += __shfl_xor_sync(0xffffffffu, s00, o);
                s01 += __shfl_xor_sync(0xffffffffu, s01, o);
            }
            if (jj < 32) {
                if (lane == jj) { v0a = s00 + bias2; v0b = s01 + bias2; }
            } else {
                if (lane == jj - 32) { v1a = s00 + bias2; v1b = s01 + bias2; }
            }
        }

        // softmax for n0 (v0a,v1a) and n1 (v0b,v1b) — interleaved
        float mxa = fmaxf(v0a, v1a);
        float mxb = fmaxf(v0b, v1b);
        #pragma unroll
        for (int o = 16; o > 0; o >>= 1) {
            mxa = fmaxf(mxa, __shfl_xor_sync(0xffffffffu, mxa, o));
            mxb = fmaxf(mxb, __shfl_xor_sync(0xffffffffu, mxb, o));
        }
        float e0a = __expf(v0a - mxa), e1a = __expf(v1a - mxa);
        float e0b = __expf(v0b - mxb), e1b = __expf(v1b - mxb);
        float sa = e0a + e1a, sb = e0b + e1b;
        #pragma unroll
        for (int o = 16; o > 0; o >>= 1) {
            sa += __shfl_xor_sync(0xffffffffu, sa, o);
            sb += __shfl_xor_sync(0xffffffffu, sb, o);
        }
        float ia = 1.f / sa, ib = 1.f / sb;
        if (lane < cnt) {
            g_attn[(size_t)bn0 * 52 + lane] = e0a * ia;
            g_attn[(size_t)bn1 * 52 + lane] = e0b * ib;
        }
        if (lane + 32 < cnt) {
            g_attn[(size_t)bn0 * 52 + lane + 32] = e1a * ia;
            g_attn[(size_t)bn1 * 52 + lane + 32] = e1b * ib;
        }
    } else {
        float u = 1.f / HL_;
        if (lane < cnt) {
            g_attn[(size_t)bn0 * 52 + lane] = u;
            g_attn[(size_t)bn1 * 52 + lane] = u;
        }
        if (lane + 32 < cnt) {
            g_attn[(size_t)bn0 * 52 + lane + 32] = u;
            g_attn[(size_t)bn1 * 52 + lane + 32] = u;
        }
    }
}

// ---------------------------------------------------------------------------
// Kernel D: out_kernel + nf writes. Block = (b, half) -> 32 n's.
// ---------------------------------------------------------------------------
#define OUT_SMEM ((32 * 52 + 64) * 4)
__global__ __launch_bounds__(512, 2) void out_kernel(
    const float* __restrict__ log_vec,
    const float* __restrict__ news_vec,
    const float* __restrict__ pos_emb,
    float* __restrict__ out,
    float* __restrict__ nf_out)
{
    extern __shared__ float sm[];
    float* attn_s = sm;                  // 32*52
    int*   act_s  = (int*)(sm + 32 * 52);

    int tid  = threadIdx.x;
    int b    = blockIdx.x >> 1;
    int half = blockIdx.x & 1;

    int cnt = g_cntflag[b] & 0xff;
    if (tid < 52) act_s[tid] = g_act[b * 52 + tid];
    __syncthreads();

    {
        const float* ag = g_attn + ((size_t)(b * NN_ + half * 32)) * 52;
        for (int i = tid; i < 32 * 52; i += 512) {
            int r = i / 52, j = i % 52;
            attn_s[i] = (j < cnt) ? ag[(size_t)r * 52 + j] : 0.f;
        }
    }

    float lf_reg[HL_];
    int d = tid;
    if (d < NEWS_) {
        for (int j = 0; j < cnt; j++) {
            int h = act_s[j];
            lf_reg[j] = (d < IN_)
                ? log_vec[(size_t)(b * HL_ + h) * IN_ + d]
                : pos_emb[(size_t)(1 + h) * POS_ + (d - IN_)];
        }
    }
    __syncthreads();

    if (d < NEWS_) {
        for (int i = 0; i < 32; i++) {
            int bn = b * NN_ + half * 32 + i;
            const float* arow = attn_s + i * 52;
            float acc = 0.f;
            int j = 0;
            for (; j + 4 <= cnt; j += 4) {
                acc += arow[j]     * lf_reg[j];
                acc += arow[j + 1] * lf_reg[j + 1];
                acc += arow[j + 2] * lf_reg[j + 2];
                acc += arow[j + 3] * lf_reg[j + 3];
            }
            for (; j < cnt; j++) acc += arow[j] * lf_reg[j];
            out[(size_t)bn * NEWS_ + d] = acc;
        }
    }

    // nf for this block's 32 rows
    {
        int rbase = b * NN_ + half * 32;
        for (int i = tid; i < 32 * NEWS_; i += 512) {
            int r = i / NEWS_, dd = i % NEWS_;
            int gr = rbase + r;
            nf_out[(size_t)gr * NEWS_ + dd] =
                (dd < IN_) ? news_vec[(size_t)gr * IN_ + dd] : pos_emb[dd - IN_];
        }
    }
}

// ---------------------------------------------------------------------------
extern "C" void kernel_launch(void* const* d_in, const int* in_sizes, int n_in,
                              void* d_out, int out_size)
{
    const float* log_vec  = (const float*)d_in[0];
    const int*   log_mask = (const int*)  d_in[1];
    const float* news_vec = (const float*)d_in[2];
    const float* pos_emb  = (const float*)d_in[3];
    const float* W1       = (const float*)d_in[4];
    const float* b1       = (const float*)d_in[5];
    const float* W2       = (const float*)d_in[6];
    const float* b2       = (const float*)d_in[7];
    float* out = (float*)d_out;

    const int NF_TOTAL = B_ * NN_ * NEWS_;
    cudaFuncSetAttribute(attn_kernel, cudaFuncAttributeMaxDynamicSharedMemorySize, ATTN_SMEM);
    cudaFuncSetAttribute(out_kernel,  cudaFuncAttributeMaxDynamicSharedMemorySize, OUT_SMEM);

    cncl_kernel<<<HL_ + 2, 256>>>(pos_emb, W1, b1, log_mask);
    gemm_mma_kernel<<<114, 256>>>(news_vec, log_vec, W1);
    attn_kernel<<<B_ * 4, 256, ATTN_SMEM>>>(W2, b2);
    out_kernel<<<B_ * 2, 512, OUT_SMEM>>>(log_vec, news_vec, pos_emb, out, out + NF_TOTAL);
}

// round 7
// speedup vs baseline: 1.2433x; 1.2433x over previous
#include <cuda_runtime.h>
#include <cuda_bf16.h>
#include <cstdint>

#define B_   64
#define NN_  64
#define HL_  50
#define IN_  384
#define POS_ 64
#define ATT_ 256
#define NEWS_ 448
#define W1COLS_ 896

// Scratch
__device__ float g_pn[B_ * NN_ * ATT_];
__device__ float g_pl[B_ * HL_ * ATT_];
__device__ float g_cn[ATT_];
__device__ float g_cl[HL_ * ATT_];
__device__ float g_attn[B_ * NN_ * 52];
__device__ int   g_act[B_ * 52];
__device__ int   g_cntflag[B_];          // cnt | (unif<<8)

__device__ __forceinline__ float tanh_fast(float x) {
    float y; asm("tanh.approx.f32 %0, %1;" : "=f"(y) : "f"(x)); return y;
}
__device__ __forceinline__ uint32_t to_tf32(float f) {
    uint32_t r; asm("cvt.rna.tf32.f32 %0, %1;" : "=r"(r) : "f"(f)); return r;
}
__device__ __forceinline__ void mma_tf32(float* c, const uint32_t* a, const uint32_t* b) {
    asm volatile(
        "mma.sync.aligned.m16n8k8.row.col.f32.tf32.tf32.f32 "
        "{%0,%1,%2,%3}, {%4,%5,%6,%7}, {%8,%9}, {%0,%1,%2,%3};"
        : "+f"(c[0]), "+f"(c[1]), "+f"(c[2]), "+f"(c[3])
        : "r"(a[0]), "r"(a[1]), "r"(a[2]), "r"(a[3]), "r"(b[0]), "r"(b[1]));
}

// ---------------------------------------------------------------------------
// Kernel A: cn / cl bias folding + per-b mask compaction
// ---------------------------------------------------------------------------
__global__ __launch_bounds__(256) void cncl_kernel(
    const float* __restrict__ pos_emb,
    const float* __restrict__ W1,
    const float* __restrict__ b1,
    const int*   __restrict__ log_mask)
{
    int a = threadIdx.x;
    int blk = blockIdx.x;
    if (blk == 0) {
        float s = b1[a];
        const float* w = W1 + a * W1COLS_ + IN_;
        #pragma unroll 8
        for (int p = 0; p < POS_; p++) s += pos_emb[p] * w[p];
        g_cn[a] = s;
    } else if (blk <= HL_) {
        int h = blk - 1;
        float s = 0.f;
        const float* w  = W1 + a * W1COLS_ + NEWS_ + IN_;
        const float* pe = pos_emb + (1 + h) * POS_;
        #pragma unroll 8
        for (int p = 0; p < POS_; p++) s += pe[p] * w[p];
        g_cl[h * ATT_ + a] = s;
    } else {
        int b = a;
        if (b < B_) {
            int c = 0;
            int buf[HL_];
            #pragma unroll
            for (int h = 0; h < HL_; h++)
                if (log_mask[b * HL_ + h] != 0) buf[c++] = h;
            int unif = (c == 0);
            if (unif) { for (int h = 0; h < HL_; h++) buf[h] = h; c = HL_; }
            for (int j = 0; j < c; j++) g_act[b * 52 + j] = buf[j];
            g_cntflag[b] = c | (unif << 8);
        }
    }
}

// ---------------------------------------------------------------------------
// Kernel B: mma.sync tf32 GEMM (unchanged)
// ---------------------------------------------------------------------------
#define BK 32
#define LDT 36
#define NKT (IN_ / BK)

__global__ __launch_bounds__(256) void gemm_mma_kernel(
    const float* __restrict__ news_vec,
    const float* __restrict__ log_vec,
    const float* __restrict__ W1)
{
    __shared__ uint32_t As[128 * LDT];
    __shared__ uint32_t Ws[128 * LDT];

    int tid  = threadIdx.x;
    int wid  = tid >> 5, lane = tid & 31;
    int gid  = lane >> 2, tig = lane & 3;
    int wm   = wid & 1;
    int wn   = wid >> 1;

    int bx   = blockIdx.x;
    int nh   = bx & 1;
    int tile = bx >> 1;
    int mode, mtile, w_off;
    const float* A;
    if (tile < 32) { mode = 0; mtile = tile;      A = news_vec; w_off = 0; }
    else           { mode = 1; mtile = tile - 32; A = log_vec;  w_off = NEWS_; }
    int n_base = nh * 128;

    int lrow = tid >> 3;
    int lf4  = tid & 7;
    const float* Abase = A  + (size_t)(mtile * 128 + lrow) * IN_ + lf4 * 4;
    const float* Wbase = W1 + (size_t)(n_base + lrow) * W1COLS_ + w_off + lf4 * 4;

    float acc[4][4][4];
    #pragma unroll
    for (int i = 0; i < 4; i++)
        #pragma unroll
        for (int j = 0; j < 4; j++)
            #pragma unroll
            for (int k = 0; k < 4; k++) acc[i][j][k] = 0.f;

    float4 aReg[4], wReg[4];
    #pragma unroll
    for (int p = 0; p < 4; p++) {
        aReg[p] = *(const float4*)(Abase + (size_t)p * 32 * IN_);
        wReg[p] = *(const float4*)(Wbase + (size_t)p * 32 * W1COLS_);
    }

    for (int kt = 0; kt < NKT; kt++) {
        #pragma unroll
        for (int p = 0; p < 4; p++) {
            uint32_t* as = &As[(p * 32 + lrow) * LDT + lf4 * 4];
            as[0] = to_tf32(aReg[p].x); as[1] = to_tf32(aReg[p].y);
            as[2] = to_tf32(aReg[p].z); as[3] = to_tf32(aReg[p].w);
            uint32_t* ws = &Ws[(p * 32 + lrow) * LDT + lf4 * 4];
            ws[0] = to_tf32(wReg[p].x); ws[1] = to_tf32(wReg[p].y);
            ws[2] = to_tf32(wReg[p].z); ws[3] = to_tf32(wReg[p].w);
        }
        __syncthreads();

        if (kt + 1 < NKT) {
            const float* An = Abase + (kt + 1) * BK;
            const float* Wn = Wbase + (kt + 1) * BK;
            #pragma unroll
            for (int p = 0; p < 4; p++) {
                aReg[p] = *(const float4*)(An + (size_t)p * 32 * IN_);
                wReg[p] = *(const float4*)(Wn + (size_t)p * 32 * W1COLS_);
            }
        }

        #pragma unroll
        for (int kk = 0; kk < BK; kk += 8) {
            uint32_t afr[4][4], bfr[4][2];
            #pragma unroll
            for (int mf = 0; mf < 4; mf++) {
                int r0 = (wm * 64 + mf * 16 + gid) * LDT + kk + tig;
                afr[mf][0] = As[r0];
                afr[mf][1] = As[r0 + 8 * LDT];
                afr[mf][2] = As[r0 + 4];
                afr[mf][3] = As[r0 + 8 * LDT + 4];
            }
            #pragma unroll
            for (int nf = 0; nf < 4; nf++) {
                int c0 = (wn * 32 + nf * 8 + gid) * LDT + kk + tig;
                bfr[nf][0] = Ws[c0];
                bfr[nf][1] = Ws[c0 + 4];
            }
            #pragma unroll
            for (int mf = 0; mf < 4; mf++)
                #pragma unroll
                for (int nf = 0; nf < 4; nf++)
                    mma_tf32(acc[mf][nf], afr[mf], bfr[nf]);
        }
        __syncthreads();
    }

    float* outp = (mode == 0) ? g_pn : g_pl;
    #pragma unroll
    for (int mf = 0; mf < 4; mf++) {
        int r0 = mtile * 128 + wm * 64 + mf * 16 + gid;
        int r1 = r0 + 8;
        const float* bias0;
        const float* bias1;
        if (mode == 0) { bias0 = g_cn; bias1 = g_cn; }
        else { bias0 = g_cl + (r0 % HL_) * ATT_; bias1 = g_cl + (r1 % HL_) * ATT_; }
        #pragma unroll
        for (int nf = 0; nf < 4; nf++) {
            int c = n_base + wn * 32 + nf * 8 + 2 * tig;
            float2 v0, v1;
            v0.x = acc[mf][nf][0] + bias0[c];
            v0.y = acc[mf][nf][1] + bias0[c + 1];
            v1.x = acc[mf][nf][2] + bias1[c];
            v1.y = acc[mf][nf][3] + bias1[c + 1];
            *(float2*)(outp + (size_t)r0 * ATT_ + c) = v0;
            *(float2*)(outp + (size_t)r1 * ATT_ + c) = v1;
        }
    }
}

// ---------------------------------------------------------------------------
// Kernel C: attn (unchanged from R6: 2 n x 2 j per warp, interleaved shfl)
// ---------------------------------------------------------------------------
#define ATTN_SMEM ((50 * 256 + 64) * 4)
__global__ __launch_bounds__(256, 2) void attn_kernel(
    const float* __restrict__ W2,
    const float* __restrict__ b2)
{
    extern __shared__ float sm[];
    float* pl_s  = sm;                 // 50*256
    int*   act_s = (int*)(sm + 12800); // 52

    int tid  = threadIdx.x;
    int b    = blockIdx.x >> 2;
    int q    = blockIdx.x & 3;
    int warp = tid >> 5, lane = tid & 31;

    int cf   = g_cntflag[b];
    int cnt  = cf & 0xff;
    int unif = cf >> 8;

    if (tid < 52) act_s[tid] = g_act[b * 52 + tid];
    __syncthreads();

    {
        int npl = cnt * 64;
        const float4* plg = (const float4*)(g_pl + (size_t)b * HL_ * ATT_);
        for (int i = tid; i < npl; i += 256) {
            int j = i >> 6, r = i & 63;
            ((float4*)pl_s)[j * 64 + r] = plg[(size_t)act_s[j] * 64 + r];
        }
    }
    float w2r[8];
    #pragma unroll
    for (int k = 0; k < 8; k++) w2r[k] = W2[lane + 32 * k];
    float bias2 = b2[0];
    __syncthreads();

    int n0 = q * 16 + warp;
    int n1 = n0 + 8;
    int bn0 = b * NN_ + n0;
    int bn1 = b * NN_ + n1;

    float pn0[8], pn1[8];
    #pragma unroll
    for (int k = 0; k < 8; k++) {
        pn0[k] = g_pn[(size_t)bn0 * ATT_ + lane + 32 * k];
        pn1[k] = g_pn[(size_t)bn1 * ATT_ + lane + 32 * k];
    }

    if (!unif) {
        float v0a = -3.0e38f, v1a = -3.0e38f;
        float v0b = -3.0e38f, v1b = -3.0e38f;
        int jj = 0;
        for (; jj + 1 < cnt; jj += 2) {
            const float* p0 = pl_s + jj * ATT_;
            const float* p1 = pl_s + (jj + 1) * ATT_;
            float s00 = 0.f, s01 = 0.f, s10 = 0.f, s11 = 0.f;
            #pragma unroll
            for (int k = 0; k < 8; k++) {
                float x0 = p0[lane + 32 * k];
                float x1 = p1[lane + 32 * k];
                s00 += tanh_fast(pn0[k] + x0) * w2r[k];
                s01 += tanh_fast(pn1[k] + x0) * w2r[k];
                s10 += tanh_fast(pn0[k] + x1) * w2r[k];
                s11 += tanh_fast(pn1[k] + x1) * w2r[k];
            }
            #pragma unroll
            for (int o = 16; o > 0; o >>= 1) {
                s00 += __shfl_xor_sync(0xffffffffu, s00, o);
                s01 += __shfl_xor_sync(0xffffffffu, s01, o);
                s10 += __shfl_xor_sync(0xffffffffu, s10, o);
                s11 += __shfl_xor_sync(0xffffffffu, s11, o);
            }
            if (jj < 32) {
                if (lane == jj) { v0a = s00 + bias2; v0b = s01 + bias2; }
            } else {
                if (lane == jj - 32) { v1a = s00 + bias2; v1b = s01 + bias2; }
            }
            int j2 = jj + 1;
            if (j2 < 32) {
                if (lane == j2) { v0a = s10 + bias2; v0b = s11 + bias2; }
            } else {
                if (lane == j2 - 32) { v1a = s10 + bias2; v1b = s11 + bias2; }
            }
        }
        if (jj < cnt) {
            const float* p0 = pl_s + jj * ATT_;
            float s00 = 0.f, s01 = 0.f;
            #pragma unroll
            for (int k = 0; k < 8; k++) {
                float x0 = p0[lane + 32 * k];
                s00 += tanh_fast(pn0[k] + x0) * w2r[k];
                s01 += tanh_fast(pn1[k] + x0) * w2r[k];
            }
            #pragma unroll
            for (int o = 16; o > 0; o >>= 1) {
                s00 += __shfl_xor_sync(0xffffffffu, s00, o);
                s01 += __shfl_xor_sync(0xffffffffu, s01, o);
            }
            if (jj < 32) {
                if (lane == jj) { v0a = s00 + bias2; v0b = s01 + bias2; }
            } else {
                if (lane == jj - 32) { v1a = s00 + bias2; v1b = s01 + bias2; }
            }
        }

        float mxa = fmaxf(v0a, v1a);
        float mxb = fmaxf(v0b, v1b);
        #pragma unroll
        for (int o = 16; o > 0; o >>= 1) {
            mxa = fmaxf(mxa, __shfl_xor_sync(0xffffffffu, mxa, o));
            mxb = fmaxf(mxb, __shfl_xor_sync(0xffffffffu, mxb, o));
        }
        float e0a = __expf(v0a - mxa), e1a = __expf(v1a - mxa);
        float e0b = __expf(v0b - mxb), e1b = __expf(v1b - mxb);
        float sa = e0a + e1a, sb = e0b + e1b;
        #pragma unroll
        for (int o = 16; o > 0; o >>= 1) {
            sa += __shfl_xor_sync(0xffffffffu, sa, o);
            sb += __shfl_xor_sync(0xffffffffu, sb, o);
        }
        float ia = 1.f / sa, ib = 1.f / sb;
        if (lane < cnt) {
            g_attn[(size_t)bn0 * 52 + lane] = e0a * ia;
            g_attn[(size_t)bn1 * 52 + lane] = e0b * ib;
        }
        if (lane + 32 < cnt) {
            g_attn[(size_t)bn0 * 52 + lane + 32] = e1a * ia;
            g_attn[(size_t)bn1 * 52 + lane + 32] = e1b * ib;
        }
    } else {
        float u = 1.f / HL_;
        if (lane < cnt) {
            g_attn[(size_t)bn0 * 52 + lane] = u;
            g_attn[(size_t)bn1 * 52 + lane] = u;
        }
        if (lane + 32 < cnt) {
            g_attn[(size_t)bn0 * 52 + lane + 32] = u;
            g_attn[(size_t)bn1 * 52 + lane + 32] = u;
        }
    }
}

// ---------------------------------------------------------------------------
// Kernel D: out_kernel (spill-free) + nf writes. Block = (b, half), 448 thr.
// lf_reg statically unrolled to 52 (predicated) -> stays in registers.
// attn rows read as LDS.128, float4 accumulator (4 FMA chains).
// ---------------------------------------------------------------------------
#define OUT_SMEM ((32 * 52 + 64) * 4)
__global__ __launch_bounds__(448, 2) void out_kernel(
    const float* __restrict__ log_vec,
    const float* __restrict__ news_vec,
    const float* __restrict__ pos_emb,
    float* __restrict__ out,
    float* __restrict__ nf_out)
{
    extern __shared__ float sm[];
    float* attn_s = sm;                  // 32 rows x 52 floats (208B rows, 16B-aligned)
    int*   act_s  = (int*)(sm + 32 * 52);

    int tid  = threadIdx.x;
    int b    = blockIdx.x >> 1;
    int half = blockIdx.x & 1;

    int cnt = g_cntflag[b] & 0xff;
    if (tid < 52) act_s[tid] = g_act[b * 52 + tid];
    __syncthreads();

    // stage attn (zero-padded to 52)
    {
        const float* ag = g_attn + ((size_t)(b * NN_ + half * 32)) * 52;
        for (int i = tid; i < 32 * 52; i += 448) {
            int r = i / 52, j = i % 52;
            attn_s[i] = (j < cnt) ? ag[(size_t)r * 52 + j] : 0.f;
        }
    }

    // lf into registers: STATIC 52-unroll, predicated -> no local spill
    int d = tid;   // 0..447, all valid
    float lf_reg[52];
    const float* lv = log_vec + (size_t)b * HL_ * IN_ + d;
    const float* pe = pos_emb + POS_ + (d - IN_);
    bool lowd = (d < IN_);
    #pragma unroll
    for (int j = 0; j < 52; j++) {
        float v = 0.f;
        if (j < cnt) {
            int h = act_s[j];
            v = lowd ? lv[(size_t)h * IN_] : pe[(size_t)h * POS_];
        }
        lf_reg[j] = v;
    }
    __syncthreads();

    // compute: out[bn,d] = attn_row(i) . lf_reg
    {
        const float4* at4 = (const float4*)attn_s;
        float* obase = out + ((size_t)(b * NN_ + half * 32)) * NEWS_ + d;
        #pragma unroll 2
        for (int i = 0; i < 32; i++) {
            float4 a4acc = make_float4(0.f, 0.f, 0.f, 0.f);
            #pragma unroll
            for (int k = 0; k < 13; k++) {
                float4 a4 = at4[i * 13 + k];
                a4acc.x += a4.x * lf_reg[4 * k];
                a4acc.y += a4.y * lf_reg[4 * k + 1];
                a4acc.z += a4.z * lf_reg[4 * k + 2];
                a4acc.w += a4.w * lf_reg[4 * k + 3];
            }
            obase[(size_t)i * NEWS_] = (a4acc.x + a4acc.y) + (a4acc.z + a4acc.w);
        }
    }

    // nf for this block's 32 rows
    {
        int rbase = b * NN_ + half * 32;
        float posv = (d >= IN_) ? pos_emb[d - IN_] : 0.f;
        #pragma unroll 4
        for (int r = 0; r < 32; r++) {
            int gr = rbase + r;
            nf_out[(size_t)gr * NEWS_ + d] =
                lowd ? news_vec[(size_t)gr * IN_ + d] : posv;
        }
    }
}

// ---------------------------------------------------------------------------
extern "C" void kernel_launch(void* const* d_in, const int* in_sizes, int n_in,
                              void* d_out, int out_size)
{
    const float* log_vec  = (const float*)d_in[0];
    const int*   log_mask = (const int*)  d_in[1];
    const float* news_vec = (const float*)d_in[2];
    const float* pos_emb  = (const float*)d_in[3];
    const float* W1       = (const float*)d_in[4];
    const float* b1       = (const float*)d_in[5];
    const float* W2       = (const float*)d_in[6];
    const float* b2       = (const float*)d_in[7];
    float* out = (float*)d_out;

    const int NF_TOTAL = B_ * NN_ * NEWS_;
    cudaFuncSetAttribute(attn_kernel, cudaFuncAttributeMaxDynamicSharedMemorySize, ATTN_SMEM);
    cudaFuncSetAttribute(out_kernel,  cudaFuncAttributeMaxDynamicSharedMemorySize, OUT_SMEM);

    cncl_kernel<<<HL_ + 2, 256>>>(pos_emb, W1, b1, log_mask);
    gemm_mma_kernel<<<114, 256>>>(news_vec, log_vec, W1);
    attn_kernel<<<B_ * 4, 256, ATTN_SMEM>>>(W2, b2);
    out_kernel<<<B_ * 2, 448, OUT_SMEM>>>(log_vec, news_vec, pos_emb, out, out + NF_TOTAL);
}

// round 8
// speedup vs baseline: 1.2782x; 1.0281x over previous
#include <cuda_runtime.h>
#include <cuda_bf16.h>
#include <cstdint>

#define B_   64
#define NN_  64
#define HL_  50
#define IN_  384
#define POS_ 64
#define ATT_ 256
#define NEWS_ 448
#define W1COLS_ 896

// Scratch
__device__ float g_pn[B_ * NN_ * ATT_];
__device__ float g_pl[B_ * HL_ * ATT_];
__device__ float g_cn[ATT_];
__device__ float g_cl[HL_ * ATT_];
__device__ float g_attn[B_ * NN_ * 52];
__device__ int   g_act[B_ * 52];
__device__ int   g_cntflag[B_];          // cnt | (unif<<8)

__device__ __forceinline__ float tanh_fast(float x) {
    float y; asm("tanh.approx.f32 %0, %1;" : "=f"(y) : "f"(x)); return y;
}
__device__ __forceinline__ uint32_t to_tf32(float f) {
    uint32_t r; asm("cvt.rna.tf32.f32 %0, %1;" : "=r"(r) : "f"(f)); return r;
}
__device__ __forceinline__ void mma_tf32(float* c, const uint32_t* a, const uint32_t* b) {
    asm volatile(
        "mma.sync.aligned.m16n8k8.row.col.f32.tf32.tf32.f32 "
        "{%0,%1,%2,%3}, {%4,%5,%6,%7}, {%8,%9}, {%0,%1,%2,%3};"
        : "+f"(c[0]), "+f"(c[1]), "+f"(c[2]), "+f"(c[3])
        : "r"(a[0]), "r"(a[1]), "r"(a[2]), "r"(a[3]), "r"(b[0]), "r"(b[1]));
}

// ---------------------------------------------------------------------------
// Kernel A: cn / cl bias folding + per-b mask compaction
// ---------------------------------------------------------------------------
__global__ __launch_bounds__(256) void cncl_kernel(
    const float* __restrict__ pos_emb,
    const float* __restrict__ W1,
    const float* __restrict__ b1,
    const int*   __restrict__ log_mask)
{
    int a = threadIdx.x;
    int blk = blockIdx.x;
    if (blk == 0) {
        float s = b1[a];
        const float* w = W1 + a * W1COLS_ + IN_;
        #pragma unroll 8
        for (int p = 0; p < POS_; p++) s += pos_emb[p] * w[p];
        g_cn[a] = s;
    } else if (blk <= HL_) {
        int h = blk - 1;
        float s = 0.f;
        const float* w  = W1 + a * W1COLS_ + NEWS_ + IN_;
        const float* pe = pos_emb + (1 + h) * POS_;
        #pragma unroll 8
        for (int p = 0; p < POS_; p++) s += pe[p] * w[p];
        g_cl[h * ATT_ + a] = s;
    } else {
        int b = a;
        if (b < B_) {
            int c = 0;
            int buf[HL_];
            #pragma unroll
            for (int h = 0; h < HL_; h++)
                if (log_mask[b * HL_ + h] != 0) buf[c++] = h;
            int unif = (c == 0);
            if (unif) { for (int h = 0; h < HL_; h++) buf[h] = h; c = HL_; }
            for (int j = 0; j < c; j++) g_act[b * 52 + j] = buf[j];
            g_cntflag[b] = c | (unif << 8);
        }
    }
}

// ---------------------------------------------------------------------------
// Kernel B: mma.sync tf32 GEMM (unchanged)
// ---------------------------------------------------------------------------
#define BK 32
#define LDT 36
#define NKT (IN_ / BK)

__global__ __launch_bounds__(256) void gemm_mma_kernel(
    const float* __restrict__ news_vec,
    const float* __restrict__ log_vec,
    const float* __restrict__ W1)
{
    __shared__ uint32_t As[128 * LDT];
    __shared__ uint32_t Ws[128 * LDT];

    int tid  = threadIdx.x;
    int wid  = tid >> 5, lane = tid & 31;
    int gid  = lane >> 2, tig = lane & 3;
    int wm   = wid & 1;
    int wn   = wid >> 1;

    int bx   = blockIdx.x;
    int nh   = bx & 1;
    int tile = bx >> 1;
    int mode, mtile, w_off;
    const float* A;
    if (tile < 32) { mode = 0; mtile = tile;      A = news_vec; w_off = 0; }
    else           { mode = 1; mtile = tile - 32; A = log_vec;  w_off = NEWS_; }
    int n_base = nh * 128;

    int lrow = tid >> 3;
    int lf4  = tid & 7;
    const float* Abase = A  + (size_t)(mtile * 128 + lrow) * IN_ + lf4 * 4;
    const float* Wbase = W1 + (size_t)(n_base + lrow) * W1COLS_ + w_off + lf4 * 4;

    float acc[4][4][4];
    #pragma unroll
    for (int i = 0; i < 4; i++)
        #pragma unroll
        for (int j = 0; j < 4; j++)
            #pragma unroll
            for (int k = 0; k < 4; k++) acc[i][j][k] = 0.f;

    float4 aReg[4], wReg[4];
    #pragma unroll
    for (int p = 0; p < 4; p++) {
        aReg[p] = *(const float4*)(Abase + (size_t)p * 32 * IN_);
        wReg[p] = *(const float4*)(Wbase + (size_t)p * 32 * W1COLS_);
    }

    for (int kt = 0; kt < NKT; kt++) {
        #pragma unroll
        for (int p = 0; p < 4; p++) {
            uint32_t* as = &As[(p * 32 + lrow) * LDT + lf4 * 4];
            as[0] = to_tf32(aReg[p].x); as[1] = to_tf32(aReg[p].y);
            as[2] = to_tf32(aReg[p].z); as[3] = to_tf32(aReg[p].w);
            uint32_t* ws = &Ws[(p * 32 + lrow) * LDT + lf4 * 4];
            ws[0] = to_tf32(wReg[p].x); ws[1] = to_tf32(wReg[p].y);
            ws[2] = to_tf32(wReg[p].z); ws[3] = to_tf32(wReg[p].w);
        }
        __syncthreads();

        if (kt + 1 < NKT) {
            const float* An = Abase + (kt + 1) * BK;
            const float* Wn = Wbase + (kt + 1) * BK;
            #pragma unroll
            for (int p = 0; p < 4; p++) {
                aReg[p] = *(const float4*)(An + (size_t)p * 32 * IN_);
                wReg[p] = *(const float4*)(Wn + (size_t)p * 32 * W1COLS_);
            }
        }

        #pragma unroll
        for (int kk = 0; kk < BK; kk += 8) {
            uint32_t afr[4][4], bfr[4][2];
            #pragma unroll
            for (int mf = 0; mf < 4; mf++) {
                int r0 = (wm * 64 + mf * 16 + gid) * LDT + kk + tig;
                afr[mf][0] = As[r0];
                afr[mf][1] = As[r0 + 8 * LDT];
                afr[mf][2] = As[r0 + 4];
                afr[mf][3] = As[r0 + 8 * LDT + 4];
            }
            #pragma unroll
            for (int nf = 0; nf < 4; nf++) {
                int c0 = (wn * 32 + nf * 8 + gid) * LDT + kk + tig;
                bfr[nf][0] = Ws[c0];
                bfr[nf][1] = Ws[c0 + 4];
            }
            #pragma unroll
            for (int mf = 0; mf < 4; mf++)
                #pragma unroll
                for (int nf = 0; nf < 4; nf++)
                    mma_tf32(acc[mf][nf], afr[mf], bfr[nf]);
        }
        __syncthreads();
    }

    float* outp = (mode == 0) ? g_pn : g_pl;
    #pragma unroll
    for (int mf = 0; mf < 4; mf++) {
        int r0 = mtile * 128 + wm * 64 + mf * 16 + gid;
        int r1 = r0 + 8;
        const float* bias0;
        const float* bias1;
        if (mode == 0) { bias0 = g_cn; bias1 = g_cn; }
        else { bias0 = g_cl + (r0 % HL_) * ATT_; bias1 = g_cl + (r1 % HL_) * ATT_; }
        #pragma unroll
        for (int nf = 0; nf < 4; nf++) {
            int c = n_base + wn * 32 + nf * 8 + 2 * tig;
            float2 v0, v1;
            v0.x = acc[mf][nf][0] + bias0[c];
            v0.y = acc[mf][nf][1] + bias0[c + 1];
            v1.x = acc[mf][nf][2] + bias1[c];
            v1.y = acc[mf][nf][3] + bias1[c + 1];
            *(float2*)(outp + (size_t)r0 * ATT_ + c) = v0;
            *(float2*)(outp + (size_t)r1 * ATT_ + c) = v1;
        }
    }
}

// ---------------------------------------------------------------------------
// Kernel C: attn (unchanged: 2 n x 2 j per warp, interleaved shfl)
// ---------------------------------------------------------------------------
#define ATTN_SMEM ((50 * 256 + 64) * 4)
__global__ __launch_bounds__(256, 2) void attn_kernel(
    const float* __restrict__ W2,
    const float* __restrict__ b2)
{
    extern __shared__ float sm[];
    float* pl_s  = sm;                 // 50*256
    int*   act_s = (int*)(sm + 12800); // 52

    int tid  = threadIdx.x;
    int b    = blockIdx.x >> 2;
    int q    = blockIdx.x & 3;
    int warp = tid >> 5, lane = tid & 31;

    int cf   = g_cntflag[b];
    int cnt  = cf & 0xff;
    int unif = cf >> 8;

    if (tid < 52) act_s[tid] = g_act[b * 52 + tid];
    __syncthreads();

    {
        int npl = cnt * 64;
        const float4* plg = (const float4*)(g_pl + (size_t)b * HL_ * ATT_);
        for (int i = tid; i < npl; i += 256) {
            int j = i >> 6, r = i & 63;
            ((float4*)pl_s)[j * 64 + r] = plg[(size_t)act_s[j] * 64 + r];
        }
    }
    float w2r[8];
    #pragma unroll
    for (int k = 0; k < 8; k++) w2r[k] = W2[lane + 32 * k];
    float bias2 = b2[0];
    __syncthreads();

    int n0 = q * 16 + warp;
    int n1 = n0 + 8;
    int bn0 = b * NN_ + n0;
    int bn1 = b * NN_ + n1;

    float pn0[8], pn1[8];
    #pragma unroll
    for (int k = 0; k < 8; k++) {
        pn0[k] = g_pn[(size_t)bn0 * ATT_ + lane + 32 * k];
        pn1[k] = g_pn[(size_t)bn1 * ATT_ + lane + 32 * k];
    }

    if (!unif) {
        float v0a = -3.0e38f, v1a = -3.0e38f;
        float v0b = -3.0e38f, v1b = -3.0e38f;
        int jj = 0;
        for (; jj + 1 < cnt; jj += 2) {
            const float* p0 = pl_s + jj * ATT_;
            const float* p1 = pl_s + (jj + 1) * ATT_;
            float s00 = 0.f, s01 = 0.f, s10 = 0.f, s11 = 0.f;
            #pragma unroll
            for (int k = 0; k < 8; k++) {
                float x0 = p0[lane + 32 * k];
                float x1 = p1[lane + 32 * k];
                s00 += tanh_fast(pn0[k] + x0) * w2r[k];
                s01 += tanh_fast(pn1[k] + x0) * w2r[k];
                s10 += tanh_fast(pn0[k] + x1) * w2r[k];
                s11 += tanh_fast(pn1[k] + x1) * w2r[k];
            }
            #pragma unroll
            for (int o = 16; o > 0; o >>= 1) {
                s00 += __shfl_xor_sync(0xffffffffu, s00, o);
                s01 += __shfl_xor_sync(0xffffffffu, s01, o);
                s10 += __shfl_xor_sync(0xffffffffu, s10, o);
                s11 += __shfl_xor_sync(0xffffffffu, s11, o);
            }
            if (jj < 32) {
                if (lane == jj) { v0a = s00 + bias2; v0b = s01 + bias2; }
            } else {
                if (lane == jj - 32) { v1a = s00 + bias2; v1b = s01 + bias2; }
            }
            int j2 = jj + 1;
            if (j2 < 32) {
                if (lane == j2) { v0a = s10 + bias2; v0b = s11 + bias2; }
            } else {
                if (lane == j2 - 32) { v1a = s10 + bias2; v1b = s11 + bias2; }
            }
        }
        if (jj < cnt) {
            const float* p0 = pl_s + jj * ATT_;
            float s00 = 0.f, s01 = 0.f;
            #pragma unroll
            for (int k = 0; k < 8; k++) {
                float x0 = p0[lane + 32 * k];
                s00 += tanh_fast(pn0[k] + x0) * w2r[k];
                s01 += tanh_fast(pn1[k] + x0) * w2r[k];
            }
            #pragma unroll
            for (int o = 16; o > 0; o >>= 1) {
                s00 += __shfl_xor_sync(0xffffffffu, s00, o);
                s01 += __shfl_xor_sync(0xffffffffu, s01, o);
            }
            if (jj < 32) {
                if (lane == jj) { v0a = s00 + bias2; v0b = s01 + bias2; }
            } else {
                if (lane == jj - 32) { v1a = s00 + bias2; v1b = s01 + bias2; }
            }
        }

        float mxa = fmaxf(v0a, v1a);
        float mxb = fmaxf(v0b, v1b);
        #pragma unroll
        for (int o = 16; o > 0; o >>= 1) {
            mxa = fmaxf(mxa, __shfl_xor_sync(0xffffffffu, mxa, o));
            mxb = fmaxf(mxb, __shfl_xor_sync(0xffffffffu, mxb, o));
        }
        float e0a = __expf(v0a - mxa), e1a = __expf(v1a - mxa);
        float e0b = __expf(v0b - mxb), e1b = __expf(v1b - mxb);
        float sa = e0a + e1a, sb = e0b + e1b;
        #pragma unroll
        for (int o = 16; o > 0; o >>= 1) {
            sa += __shfl_xor_sync(0xffffffffu, sa, o);
            sb += __shfl_xor_sync(0xffffffffu, sb, o);
        }
        float ia = 1.f / sa, ib = 1.f / sb;
        if (lane < cnt) {
            g_attn[(size_t)bn0 * 52 + lane] = e0a * ia;
            g_attn[(size_t)bn1 * 52 + lane] = e0b * ib;
        }
        if (lane + 32 < cnt) {
            g_attn[(size_t)bn0 * 52 + lane + 32] = e1a * ia;
            g_attn[(size_t)bn1 * 52 + lane + 32] = e1b * ib;
        }
    } else {
        float u = 1.f / HL_;
        if (lane < cnt) {
            g_attn[(size_t)bn0 * 52 + lane] = u;
            g_attn[(size_t)bn1 * 52 + lane] = u;
        }
        if (lane + 32 < cnt) {
            g_attn[(size_t)bn0 * 52 + lane + 32] = u;
            g_attn[(size_t)bn1 * 52 + lane + 32] = u;
        }
    }
}

// ---------------------------------------------------------------------------
// Kernel D: out_kernel. Block = (b, quarter) -> 16 n's, 448 thr, grid 256.
// lf_reg static 52-unroll (spill-free); attn rows via LDS.128.
// ---------------------------------------------------------------------------
#define OUT_SMEM ((16 * 52 + 64) * 4)
__global__ __launch_bounds__(448, 2) void out_kernel(
    const float* __restrict__ log_vec,
    const float* __restrict__ news_vec,
    const float* __restrict__ pos_emb,
    float* __restrict__ out,
    float* __restrict__ nf_out)
{
    extern __shared__ float sm[];
    float* attn_s = sm;                  // 16 rows x 52 floats
    int*   act_s  = (int*)(sm + 16 * 52);

    int tid = threadIdx.x;
    int b   = blockIdx.x >> 2;
    int q   = blockIdx.x & 3;

    int cnt = g_cntflag[b] & 0xff;
    if (tid < 52) act_s[tid] = g_act[b * 52 + tid];
    __syncthreads();

    // stage attn (zero-padded to 52)
    {
        const float* ag = g_attn + ((size_t)(b * NN_ + q * 16)) * 52;
        for (int i = tid; i < 16 * 52; i += 448) {
            int r = i / 52, j = i % 52;
            attn_s[i] = (j < cnt) ? ag[(size_t)r * 52 + j] : 0.f;
        }
    }

    // lf into registers: STATIC 52-unroll, predicated -> no local spill
    int d = tid;   // 0..447
    float lf_reg[52];
    const float* lv = log_vec + (size_t)b * HL_ * IN_ + d;
    const float* pe = pos_emb + POS_ + (d - IN_);
    bool lowd = (d < IN_);
    #pragma unroll
    for (int j = 0; j < 52; j++) {
        float v = 0.f;
        if (j < cnt) {
            int h = act_s[j];
            v = lowd ? lv[(size_t)h * IN_] : pe[(size_t)h * POS_];
        }
        lf_reg[j] = v;
    }
    __syncthreads();

    // compute: out[bn,d] = attn_row(i) . lf_reg
    {
        const float4* at4 = (const float4*)attn_s;
        float* obase = out + ((size_t)(b * NN_ + q * 16)) * NEWS_ + d;
        #pragma unroll 4
        for (int i = 0; i < 16; i++) {
            float4 a4acc = make_float4(0.f, 0.f, 0.f, 0.f);
            #pragma unroll
            for (int k = 0; k < 13; k++) {
                float4 a4 = at4[i * 13 + k];
                a4acc.x += a4.x * lf_reg[4 * k];
                a4acc.y += a4.y * lf_reg[4 * k + 1];
                a4acc.z += a4.z * lf_reg[4 * k + 2];
                a4acc.w += a4.w * lf_reg[4 * k + 3];
            }
            obase[(size_t)i * NEWS_] = (a4acc.x + a4acc.y) + (a4acc.z + a4acc.w);
        }
    }

    // nf for this block's 16 rows
    {
        int rbase = b * NN_ + q * 16;
        float posv = (d >= IN_) ? pos_emb[d - IN_] : 0.f;
        #pragma unroll 4
        for (int r = 0; r < 16; r++) {
            int gr = rbase + r;
            nf_out[(size_t)gr * NEWS_ + d] =
                lowd ? news_vec[(size_t)gr * IN_ + d] : posv;
        }
    }
}

// ---------------------------------------------------------------------------
extern "C" void kernel_launch(void* const* d_in, const int* in_sizes, int n_in,
                              void* d_out, int out_size)
{
    const float* log_vec  = (const float*)d_in[0];
    const int*   log_mask = (const int*)  d_in[1];
    const float* news_vec = (const float*)d_in[2];
    const float* pos_emb  = (const float*)d_in[3];
    const float* W1       = (const float*)d_in[4];
    const float* b1       = (const float*)d_in[5];
    const float* W2       = (const float*)d_in[6];
    const float* b2       = (const float*)d_in[7];
    float* out = (float*)d_out;

    const int NF_TOTAL = B_ * NN_ * NEWS_;
    cudaFuncSetAttribute(attn_kernel, cudaFuncAttributeMaxDynamicSharedMemorySize, ATTN_SMEM);
    cudaFuncSetAttribute(out_kernel,  cudaFuncAttributeMaxDynamicSharedMemorySize, OUT_SMEM);

    cncl_kernel<<<HL_ + 2, 256>>>(pos_emb, W1, b1, log_mask);
    gemm_mma_kernel<<<114, 256>>>(news_vec, log_vec, W1);
    attn_kernel<<<B_ * 4, 256, ATTN_SMEM>>>(W2, b2);
    out_kernel<<<B_ * 4, 448, OUT_SMEM>>>(log_vec, news_vec, pos_emb, out, out + NF_TOTAL);
}

// round 9
// speedup vs baseline: 1.3257x; 1.0371x over previous
#include <cuda_runtime.h>
#include <cuda_bf16.h>
#include <cstdint>

#define B_   64
#define NN_  64
#define HL_  50
#define IN_  384
#define POS_ 64
#define ATT_ 256
#define NEWS_ 448
#define W1COLS_ 896

// Scratch
__device__ float g_pn[B_ * NN_ * ATT_];
__device__ float g_pl[B_ * HL_ * ATT_];
__device__ float g_cn[ATT_];
__device__ float g_cl[HL_ * ATT_];
__device__ int   g_act[B_ * 52];
__device__ int   g_cntflag[B_];          // cnt | (unif<<8)

__device__ __forceinline__ float tanh_fast(float x) {
    float y; asm("tanh.approx.f32 %0, %1;" : "=f"(y) : "f"(x)); return y;
}
__device__ __forceinline__ uint32_t to_tf32(float f) {
    uint32_t r; asm("cvt.rna.tf32.f32 %0, %1;" : "=r"(r) : "f"(f)); return r;
}
__device__ __forceinline__ void mma_tf32(float* c, const uint32_t* a, const uint32_t* b) {
    asm volatile(
        "mma.sync.aligned.m16n8k8.row.col.f32.tf32.tf32.f32 "
        "{%0,%1,%2,%3}, {%4,%5,%6,%7}, {%8,%9}, {%0,%1,%2,%3};"
        : "+f"(c[0]), "+f"(c[1]), "+f"(c[2]), "+f"(c[3])
        : "r"(a[0]), "r"(a[1]), "r"(a[2]), "r"(a[3]), "r"(b[0]), "r"(b[1]));
}

// ---------------------------------------------------------------------------
// Kernel A: cn / cl bias folding + per-b mask compaction
// ---------------------------------------------------------------------------
__global__ __launch_bounds__(256) void cncl_kernel(
    const float* __restrict__ pos_emb,
    const float* __restrict__ W1,
    const float* __restrict__ b1,
    const int*   __restrict__ log_mask)
{
    int a = threadIdx.x;
    int blk = blockIdx.x;
    if (blk == 0) {
        float s = b1[a];
        const float* w = W1 + a * W1COLS_ + IN_;
        #pragma unroll 8
        for (int p = 0; p < POS_; p++) s += pos_emb[p] * w[p];
        g_cn[a] = s;
    } else if (blk <= HL_) {
        int h = blk - 1;
        float s = 0.f;
        const float* w  = W1 + a * W1COLS_ + NEWS_ + IN_;
        const float* pe = pos_emb + (1 + h) * POS_;
        #pragma unroll 8
        for (int p = 0; p < POS_; p++) s += pe[p] * w[p];
        g_cl[h * ATT_ + a] = s;
    } else {
        int b = a;
        if (b < B_) {
            int c = 0;
            int buf[HL_];
            #pragma unroll
            for (int h = 0; h < HL_; h++)
                if (log_mask[b * HL_ + h] != 0) buf[c++] = h;
            int unif = (c == 0);
            if (unif) { for (int h = 0; h < HL_; h++) buf[h] = h; c = HL_; }
            for (int j = 0; j < c; j++) g_act[b * 52 + j] = buf[j];
            g_cntflag[b] = c | (unif << 8);
        }
    }
}

// ---------------------------------------------------------------------------
// Kernel B: mma.sync tf32 GEMM (unchanged)
// ---------------------------------------------------------------------------
#define BK 32
#define LDT 36
#define NKT (IN_ / BK)

__global__ __launch_bounds__(256) void gemm_mma_kernel(
    const float* __restrict__ news_vec,
    const float* __restrict__ log_vec,
    const float* __restrict__ W1)
{
    __shared__ uint32_t As[128 * LDT];
    __shared__ uint32_t Ws[128 * LDT];

    int tid  = threadIdx.x;
    int wid  = tid >> 5, lane = tid & 31;
    int gid  = lane >> 2, tig = lane & 3;
    int wm   = wid & 1;
    int wn   = wid >> 1;

    int bx   = blockIdx.x;
    int nh   = bx & 1;
    int tile = bx >> 1;
    int mode, mtile, w_off;
    const float* A;
    if (tile < 32) { mode = 0; mtile = tile;      A = news_vec; w_off = 0; }
    else           { mode = 1; mtile = tile - 32; A = log_vec;  w_off = NEWS_; }
    int n_base = nh * 128;

    int lrow = tid >> 3;
    int lf4  = tid & 7;
    const float* Abase = A  + (size_t)(mtile * 128 + lrow) * IN_ + lf4 * 4;
    const float* Wbase = W1 + (size_t)(n_base + lrow) * W1COLS_ + w_off + lf4 * 4;

    float acc[4][4][4];
    #pragma unroll
    for (int i = 0; i < 4; i++)
        #pragma unroll
        for (int j = 0; j < 4; j++)
            #pragma unroll
            for (int k = 0; k < 4; k++) acc[i][j][k] = 0.f;

    float4 aReg[4], wReg[4];
    #pragma unroll
    for (int p = 0; p < 4; p++) {
        aReg[p] = *(const float4*)(Abase + (size_t)p * 32 * IN_);
        wReg[p] = *(const float4*)(Wbase + (size_t)p * 32 * W1COLS_);
    }

    for (int kt = 0; kt < NKT; kt++) {
        #pragma unroll
        for (int p = 0; p < 4; p++) {
            uint32_t* as = &As[(p * 32 + lrow) * LDT + lf4 * 4];
            as[0] = to_tf32(aReg[p].x); as[1] = to_tf32(aReg[p].y);
            as[2] = to_tf32(aReg[p].z); as[3] = to_tf32(aReg[p].w);
            uint32_t* ws = &Ws[(p * 32 + lrow) * LDT + lf4 * 4];
            ws[0] = to_tf32(wReg[p].x); ws[1] = to_tf32(wReg[p].y);
            ws[2] = to_tf32(wReg[p].z); ws[3] = to_tf32(wReg[p].w);
        }
        __syncthreads();

        if (kt + 1 < NKT) {
            const float* An = Abase + (kt + 1) * BK;
            const float* Wn = Wbase + (kt + 1) * BK;
            #pragma unroll
            for (int p = 0; p < 4; p++) {
                aReg[p] = *(const float4*)(An + (size_t)p * 32 * IN_);
                wReg[p] = *(const float4*)(Wn + (size_t)p * 32 * W1COLS_);
            }
        }

        #pragma unroll
        for (int kk = 0; kk < BK; kk += 8) {
            uint32_t afr[4][4], bfr[4][2];
            #pragma unroll
            for (int mf = 0; mf < 4; mf++) {
                int r0 = (wm * 64 + mf * 16 + gid) * LDT + kk + tig;
                afr[mf][0] = As[r0];
                afr[mf][1] = As[r0 + 8 * LDT];
                afr[mf][2] = As[r0 + 4];
                afr[mf][3] = As[r0 + 8 * LDT + 4];
            }
            #pragma unroll
            for (int nf = 0; nf < 4; nf++) {
                int c0 = (wn * 32 + nf * 8 + gid) * LDT + kk + tig;
                bfr[nf][0] = Ws[c0];
                bfr[nf][1] = Ws[c0 + 4];
            }
            #pragma unroll
            for (int mf = 0; mf < 4; mf++)
                #pragma unroll
                for (int nf = 0; nf < 4; nf++)
                    mma_tf32(acc[mf][nf], afr[mf], bfr[nf]);
        }
        __syncthreads();
    }

    float* outp = (mode == 0) ? g_pn : g_pl;
    #pragma unroll
    for (int mf = 0; mf < 4; mf++) {
        int r0 = mtile * 128 + wm * 64 + mf * 16 + gid;
        int r1 = r0 + 8;
        const float* bias0;
        const float* bias1;
        if (mode == 0) { bias0 = g_cn; bias1 = g_cn; }
        else { bias0 = g_cl + (r0 % HL_) * ATT_; bias1 = g_cl + (r1 % HL_) * ATT_; }
        #pragma unroll
        for (int nf = 0; nf < 4; nf++) {
            int c = n_base + wn * 32 + nf * 8 + 2 * tig;
            float2 v0, v1;
            v0.x = acc[mf][nf][0] + bias0[c];
            v0.y = acc[mf][nf][1] + bias0[c + 1];
            v1.x = acc[mf][nf][2] + bias1[c];
            v1.y = acc[mf][nf][3] + bias1[c + 1];
            *(float2*)(outp + (size_t)r0 * ATT_ + c) = v0;
            *(float2*)(outp + (size_t)r1 * ATT_ + c) = v1;
        }
    }
}

// ---------------------------------------------------------------------------
// Kernel C: FUSED attn + out. Block = (b, quarter) -> 16 n's, 448 threads.
// Phase B: 14 warps compute logits+softmax for 16 n's -> attn_s (smem only).
// Phase C: spill-free weighted-sum epilogue + nf writes.
// ---------------------------------------------------------------------------
#define FUSE_SMEM ((50 * 256 + 16 * 52 + 64) * 4)
__global__ __launch_bounds__(448, 2) void fused_kernel(
    const float* __restrict__ log_vec,
    const float* __restrict__ news_vec,
    const float* __restrict__ pos_emb,
    const float* __restrict__ W2,
    const float* __restrict__ b2,
    float* __restrict__ out,
    float* __restrict__ nf_out)
{
    extern __shared__ float sm[];
    float* pl_s   = sm;                        // 50*256
    float* attn_s = sm + 50 * 256;             // 16*52 (zero-padded)
    int*   act_s  = (int*)(sm + 50 * 256 + 16 * 52);

    int tid  = threadIdx.x;
    int b    = blockIdx.x >> 2;
    int q    = blockIdx.x & 3;
    int warp = tid >> 5, lane = tid & 31;

    int cf   = g_cntflag[b];
    int cnt  = cf & 0xff;
    int unif = cf >> 8;

    if (tid < 52) act_s[tid] = g_act[b * 52 + tid];
    __syncthreads();

    // stage compact pl
    {
        int npl = cnt * 64;
        const float4* plg = (const float4*)(g_pl + (size_t)b * HL_ * ATT_);
        for (int i = tid; i < npl; i += 448) {
            int j = i >> 6, r = i & 63;
            ((float4*)pl_s)[j * 64 + r] = plg[(size_t)act_s[j] * 64 + r];
        }
    }
    float w2r[8];
    #pragma unroll
    for (int k = 0; k < 8; k++) w2r[k] = W2[lane + 32 * k];
    float bias2 = b2[0];
    __syncthreads();

    // ---- Phase B: attn rows -> attn_s. warps 0..13, n = warp (+14) ----
    for (int nn = warp; nn < 16; nn += 14) {
        int bn = b * NN_ + q * 16 + nn;
        float pnr[8];
        #pragma unroll
        for (int k = 0; k < 8; k++) pnr[k] = g_pn[(size_t)bn * ATT_ + lane + 32 * k];

        float* arow = attn_s + nn * 52;
        if (!unif) {
            float v0 = -3.0e38f, v1 = -3.0e38f;
            int jj = 0;
            for (; jj + 1 < cnt; jj += 2) {
                const float* p0 = pl_s + jj * ATT_;
                const float* p1 = pl_s + (jj + 1) * ATT_;
                float s0 = 0.f, s1 = 0.f;
                #pragma unroll
                for (int k = 0; k < 8; k++) {
                    s0 += tanh_fast(pnr[k] + p0[lane + 32 * k]) * w2r[k];
                    s1 += tanh_fast(pnr[k] + p1[lane + 32 * k]) * w2r[k];
                }
                #pragma unroll
                for (int o = 16; o > 0; o >>= 1) {
                    s0 += __shfl_xor_sync(0xffffffffu, s0, o);
                    s1 += __shfl_xor_sync(0xffffffffu, s1, o);
                }
                if (jj < 32)      { if (lane == jj)      v0 = s0 + bias2; }
                else              { if (lane == jj - 32) v1 = s0 + bias2; }
                int j2 = jj + 1;
                if (j2 < 32)      { if (lane == j2)      v0 = s1 + bias2; }
                else              { if (lane == j2 - 32) v1 = s1 + bias2; }
            }
            if (jj < cnt) {
                const float* p0 = pl_s + jj * ATT_;
                float s0 = 0.f;
                #pragma unroll
                for (int k = 0; k < 8; k++)
                    s0 += tanh_fast(pnr[k] + p0[lane + 32 * k]) * w2r[k];
                #pragma unroll
                for (int o = 16; o > 0; o >>= 1)
                    s0 += __shfl_xor_sync(0xffffffffu, s0, o);
                if (jj < 32)      { if (lane == jj)      v0 = s0 + bias2; }
                else              { if (lane == jj - 32) v1 = s0 + bias2; }
            }
            float mx = fmaxf(v0, v1);
            #pragma unroll
            for (int o = 16; o > 0; o >>= 1)
                mx = fmaxf(mx, __shfl_xor_sync(0xffffffffu, mx, o));
            float e0 = __expf(v0 - mx), e1 = __expf(v1 - mx);
            float sv = e0 + e1;
            #pragma unroll
            for (int o = 16; o > 0; o >>= 1)
                sv += __shfl_xor_sync(0xffffffffu, sv, o);
            float inv = 1.f / sv;
            arow[lane] = (lane < cnt) ? e0 * inv : 0.f;
            if (lane < 20) arow[lane + 32] = (lane + 32 < cnt) ? e1 * inv : 0.f;
        } else {
            float u = 1.f / HL_;
            arow[lane] = (lane < cnt) ? u : 0.f;
            if (lane < 20) arow[lane + 32] = (lane + 32 < cnt) ? u : 0.f;
        }
    }
    __syncthreads();

    // ---- Phase C: lf gather (spill-free) + weighted sum ----
    int d = tid;   // 0..447
    float lf_reg[52];
    {
        const float* lv = log_vec + (size_t)b * HL_ * IN_ + d;
        const float* pe = pos_emb + POS_ + (d - IN_);
        bool lowd = (d < IN_);
        #pragma unroll
        for (int j = 0; j < 52; j++) {
            float v = 0.f;
            if (j < cnt) {
                int h = act_s[j];
                v = lowd ? lv[(size_t)h * IN_] : pe[(size_t)h * POS_];
            }
            lf_reg[j] = v;
        }
    }

    {
        const float4* at4 = (const float4*)attn_s;
        float* obase = out + ((size_t)(b * NN_ + q * 16)) * NEWS_ + d;
        #pragma unroll 4
        for (int i = 0; i < 16; i++) {
            float4 a4acc = make_float4(0.f, 0.f, 0.f, 0.f);
            #pragma unroll
            for (int k = 0; k < 13; k++) {
                float4 a4 = at4[i * 13 + k];
                a4acc.x += a4.x * lf_reg[4 * k];
                a4acc.y += a4.y * lf_reg[4 * k + 1];
                a4acc.z += a4.z * lf_reg[4 * k + 2];
                a4acc.w += a4.w * lf_reg[4 * k + 3];
            }
            obase[(size_t)i * NEWS_] = (a4acc.x + a4acc.y) + (a4acc.z + a4acc.w);
        }
    }

    // nf for this block's 16 rows
    {
        int rbase = b * NN_ + q * 16;
        bool lowd = (d < IN_);
        float posv = lowd ? 0.f : pos_emb[d - IN_];
        #pragma unroll 4
        for (int r = 0; r < 16; r++) {
            int gr = rbase + r;
            nf_out[(size_t)gr * NEWS_ + d] =
                lowd ? news_vec[(size_t)gr * IN_ + d] : posv;
        }
    }
}

// ---------------------------------------------------------------------------
extern "C" void kernel_launch(void* const* d_in, const int* in_sizes, int n_in,
                              void* d_out, int out_size)
{
    const float* log_vec  = (const float*)d_in[0];
    const int*   log_mask = (const int*)  d_in[1];
    const float* news_vec = (const float*)d_in[2];
    const float* pos_emb  = (const float*)d_in[3];
    const float* W1       = (const float*)d_in[4];
    const float* b1       = (const float*)d_in[5];
    const float* W2       = (const float*)d_in[6];
    const float* b2       = (const float*)d_in[7];
    float* out = (float*)d_out;

    const int NF_TOTAL = B_ * NN_ * NEWS_;
    cudaFuncSetAttribute(fused_kernel, cudaFuncAttributeMaxDynamicSharedMemorySize, FUSE_SMEM);

    cncl_kernel<<<HL_ + 2, 256>>>(pos_emb, W1, b1, log_mask);
    gemm_mma_kernel<<<114, 256>>>(news_vec, log_vec, W1);
    fused_kernel<<<B_ * 4, 448, FUSE_SMEM>>>(log_vec, news_vec, pos_emb, W2, b2,
                                             out, out + NF_TOTAL);
}

// round 10
// speedup vs baseline: 1.4958x; 1.1283x over previous
#include <cuda_runtime.h>
#include <cuda_bf16.h>
#include <cstdint>

#define B_   64
#define NN_  64
#define HL_  50
#define IN_  384
#define POS_ 64
#define ATT_ 256
#define NEWS_ 448
#define W1COLS_ 896

// Scratch
__device__ float g_pn[B_ * NN_ * ATT_];
__device__ float g_pl[B_ * HL_ * ATT_];
__device__ float g_cn[ATT_];
__device__ float g_cl[HL_ * ATT_];
__device__ int   g_act[B_ * 52];
__device__ int   g_cntflag[B_];          // cnt | (unif<<8)

__device__ __forceinline__ float tanh_fast(float x) {
    float y; asm("tanh.approx.f32 %0, %1;" : "=f"(y) : "f"(x)); return y;
}
__device__ __forceinline__ uint32_t to_tf32(float f) {
    uint32_t r; asm("cvt.rna.tf32.f32 %0, %1;" : "=r"(r) : "f"(f)); return r;
}
__device__ __forceinline__ void mma_tf32(float* c, const uint32_t* a, const uint32_t* b) {
    asm volatile(
        "mma.sync.aligned.m16n8k8.row.col.f32.tf32.tf32.f32 "
        "{%0,%1,%2,%3}, {%4,%5,%6,%7}, {%8,%9}, {%0,%1,%2,%3};"
        : "+f"(c[0]), "+f"(c[1]), "+f"(c[2]), "+f"(c[3])
        : "r"(a[0]), "r"(a[1]), "r"(a[2]), "r"(a[3]), "r"(b[0]), "r"(b[1]));
}

// ---------------------------------------------------------------------------
// Kernel A: cncl2 — coalesced bias folding + ballot-based mask compaction.
// Blocks 0..15: a-range [blk*16, blk*16+16): stage W tiles + pos_emb to smem,
//   compute cn (16 outputs) and cl (50x16 outputs) from smem.
// Block 16: mask compaction via warp ballots (1 warp : 8 b's).
// ---------------------------------------------------------------------------
__global__ __launch_bounds__(256) void cncl2_kernel(
    const float* __restrict__ pos_emb,
    const float* __restrict__ W1,
    const float* __restrict__ b1,
    const int*   __restrict__ log_mask)
{
    int blk = blockIdx.x;
    int tid = threadIdx.x;

    if (blk == 16) {
        int warp = tid >> 5, lane = tid & 31;
        for (int b = warp; b < B_; b += 8) {
            int m1 = log_mask[b * HL_ + lane] != 0;                       // h = lane
            int m2 = (lane < 18) ? (log_mask[b * HL_ + 32 + lane] != 0) : 0;
            unsigned bb0 = __ballot_sync(0xffffffffu, m1);
            unsigned bb1 = __ballot_sync(0xffffffffu, m2);
            int cnt = __popc(bb0) + __popc(bb1);
            if (cnt == 0) {
                if (lane < HL_) g_act[b * 52 + lane] = lane;
                if (lane < 18)  g_act[b * 52 + 32 + lane] = 32 + lane;
                if (lane == 0)  g_cntflag[b] = HL_ | (1 << 8);
            } else {
                if (m1) {
                    int idx = __popc(bb0 & ((1u << lane) - 1u));
                    g_act[b * 52 + idx] = lane;
                }
                if (m2) {
                    int idx = __popc(bb0) + __popc(bb1 & ((1u << lane) - 1u));
                    g_act[b * 52 + idx] = 32 + lane;
                }
                if (lane == 0) g_cntflag[b] = cnt;
            }
        }
        return;
    }

    __shared__ float wl_t[64 * 16];   // transposed [p][a_local] -> conflict-free
    __shared__ float wn_s[16 * 64];   // row-major (cn only uses 16 threads)
    __shared__ float pe_s[51 * 64];   // pos_emb rows 0..50

    int a0 = blk * 16;
    {
        int row = tid >> 4, f4 = tid & 15;
        const float4* wsrc = (const float4*)(W1 + (size_t)(a0 + row) * W1COLS_);
        float4 vn = wsrc[IN_ / 4 + f4];              // cols 384..447
        float4 vl = wsrc[(NEWS_ + IN_) / 4 + f4];    // cols 832..895
        ((float4*)wn_s)[row * 16 + f4] = vn;
        wl_t[(f4 * 4 + 0) * 16 + row] = vl.x;
        wl_t[(f4 * 4 + 1) * 16 + row] = vl.y;
        wl_t[(f4 * 4 + 2) * 16 + row] = vl.z;
        wl_t[(f4 * 4 + 3) * 16 + row] = vl.w;
    }
    for (int i = tid; i < 51 * 16; i += 256)
        ((float4*)pe_s)[i] = ((const float4*)pos_emb)[i];
    __syncthreads();

    // cn for this block's 16 a's
    if (tid < 16) {
        int a = a0 + tid;
        float s = b1[a];
        #pragma unroll
        for (int p = 0; p < POS_; p++) s += pe_s[p] * wn_s[tid * 64 + p];
        g_cn[a] = s;
    }

    // cl: 50 x 16 outputs
    for (int idx = tid; idx < HL_ * 16; idx += 256) {
        int h = idx >> 4, al = idx & 15;
        const float* per = pe_s + (1 + h) * 64;
        float s = 0.f;
        #pragma unroll
        for (int p = 0; p < POS_; p++) s += per[p] * wl_t[p * 16 + al];
        g_cl[h * ATT_ + (a0 + al)] = s;
    }
}

// ---------------------------------------------------------------------------
// Kernel B: mma.sync tf32 GEMM (unchanged)
// ---------------------------------------------------------------------------
#define BK 32
#define LDT 36
#define NKT (IN_ / BK)

__global__ __launch_bounds__(256) void gemm_mma_kernel(
    const float* __restrict__ news_vec,
    const float* __restrict__ log_vec,
    const float* __restrict__ W1)
{
    __shared__ uint32_t As[128 * LDT];
    __shared__ uint32_t Ws[128 * LDT];

    int tid  = threadIdx.x;
    int wid  = tid >> 5, lane = tid & 31;
    int gid  = lane >> 2, tig = lane & 3;
    int wm   = wid & 1;
    int wn   = wid >> 1;

    int bx   = blockIdx.x;
    int nh   = bx & 1;
    int tile = bx >> 1;
    int mode, mtile, w_off;
    const float* A;
    if (tile < 32) { mode = 0; mtile = tile;      A = news_vec; w_off = 0; }
    else           { mode = 1; mtile = tile - 32; A = log_vec;  w_off = NEWS_; }
    int n_base = nh * 128;

    int lrow = tid >> 3;
    int lf4  = tid & 7;
    const float* Abase = A  + (size_t)(mtile * 128 + lrow) * IN_ + lf4 * 4;
    const float* Wbase = W1 + (size_t)(n_base + lrow) * W1COLS_ + w_off + lf4 * 4;

    float acc[4][4][4];
    #pragma unroll
    for (int i = 0; i < 4; i++)
        #pragma unroll
        for (int j = 0; j < 4; j++)
            #pragma unroll
            for (int k = 0; k < 4; k++) acc[i][j][k] = 0.f;

    float4 aReg[4], wReg[4];
    #pragma unroll
    for (int p = 0; p < 4; p++) {
        aReg[p] = *(const float4*)(Abase + (size_t)p * 32 * IN_);
        wReg[p] = *(const float4*)(Wbase + (size_t)p * 32 * W1COLS_);
    }

    for (int kt = 0; kt < NKT; kt++) {
        #pragma unroll
        for (int p = 0; p < 4; p++) {
            uint32_t* as = &As[(p * 32 + lrow) * LDT + lf4 * 4];
            as[0] = to_tf32(aReg[p].x); as[1] = to_tf32(aReg[p].y);
            as[2] = to_tf32(aReg[p].z); as[3] = to_tf32(aReg[p].w);
            uint32_t* ws = &Ws[(p * 32 + lrow) * LDT + lf4 * 4];
            ws[0] = to_tf32(wReg[p].x); ws[1] = to_tf32(wReg[p].y);
            ws[2] = to_tf32(wReg[p].z); ws[3] = to_tf32(wReg[p].w);
        }
        __syncthreads();

        if (kt + 1 < NKT) {
            const float* An = Abase + (kt + 1) * BK;
            const float* Wn = Wbase + (kt + 1) * BK;
            #pragma unroll
            for (int p = 0; p < 4; p++) {
                aReg[p] = *(const float4*)(An + (size_t)p * 32 * IN_);
                wReg[p] = *(const float4*)(Wn + (size_t)p * 32 * W1COLS_);
            }
        }

        #pragma unroll
        for (int kk = 0; kk < BK; kk += 8) {
            uint32_t afr[4][4], bfr[4][2];
            #pragma unroll
            for (int mf = 0; mf < 4; mf++) {
                int r0 = (wm * 64 + mf * 16 + gid) * LDT + kk + tig;
                afr[mf][0] = As[r0];
                afr[mf][1] = As[r0 + 8 * LDT];
                afr[mf][2] = As[r0 + 4];
                afr[mf][3] = As[r0 + 8 * LDT + 4];
            }
            #pragma unroll
            for (int nf = 0; nf < 4; nf++) {
                int c0 = (wn * 32 + nf * 8 + gid) * LDT + kk + tig;
                bfr[nf][0] = Ws[c0];
                bfr[nf][1] = Ws[c0 + 4];
            }
            #pragma unroll
            for (int mf = 0; mf < 4; mf++)
                #pragma unroll
                for (int nf = 0; nf < 4; nf++)
                    mma_tf32(acc[mf][nf], afr[mf], bfr[nf]);
        }
        __syncthreads();
    }

    float* outp = (mode == 0) ? g_pn : g_pl;
    #pragma unroll
    for (int mf = 0; mf < 4; mf++) {
        int r0 = mtile * 128 + wm * 64 + mf * 16 + gid;
        int r1 = r0 + 8;
        const float* bias0;
        const float* bias1;
        if (mode == 0) { bias0 = g_cn; bias1 = g_cn; }
        else { bias0 = g_cl + (r0 % HL_) * ATT_; bias1 = g_cl + (r1 % HL_) * ATT_; }
        #pragma unroll
        for (int nf = 0; nf < 4; nf++) {
            int c = n_base + wn * 32 + nf * 8 + 2 * tig;
            float2 v0, v1;
            v0.x = acc[mf][nf][0] + bias0[c];
            v0.y = acc[mf][nf][1] + bias0[c + 1];
            v1.x = acc[mf][nf][2] + bias1[c];
            v1.y = acc[mf][nf][3] + bias1[c + 1];
            *(float2*)(outp + (size_t)r0 * ATT_ + c) = v0;
            *(float2*)(outp + (size_t)r1 * ATT_ + c) = v1;
        }
    }
}

// ---------------------------------------------------------------------------
// Kernel C: FUSED attn + out (unchanged from R9)
// ---------------------------------------------------------------------------
#define FUSE_SMEM ((50 * 256 + 16 * 52 + 64) * 4)
__global__ __launch_bounds__(448, 2) void fused_kernel(
    const float* __restrict__ log_vec,
    const float* __restrict__ news_vec,
    const float* __restrict__ pos_emb,
    const float* __restrict__ W2,
    const float* __restrict__ b2,
    float* __restrict__ out,
    float* __restrict__ nf_out)
{
    extern __shared__ float sm[];
    float* pl_s   = sm;                        // 50*256
    float* attn_s = sm + 50 * 256;             // 16*52 (zero-padded)
    int*   act_s  = (int*)(sm + 50 * 256 + 16 * 52);

    int tid  = threadIdx.x;
    int b    = blockIdx.x >> 2;
    int q    = blockIdx.x & 3;
    int warp = tid >> 5, lane = tid & 31;

    int cf   = g_cntflag[b];
    int cnt  = cf & 0xff;
    int unif = cf >> 8;

    if (tid < 52) act_s[tid] = g_act[b * 52 + tid];
    __syncthreads();

    // stage compact pl
    {
        int npl = cnt * 64;
        const float4* plg = (const float4*)(g_pl + (size_t)b * HL_ * ATT_);
        for (int i = tid; i < npl; i += 448) {
            int j = i >> 6, r = i & 63;
            ((float4*)pl_s)[j * 64 + r] = plg[(size_t)act_s[j] * 64 + r];
        }
    }
    float w2r[8];
    #pragma unroll
    for (int k = 0; k < 8; k++) w2r[k] = W2[lane + 32 * k];
    float bias2 = b2[0];
    __syncthreads();

    // ---- Phase B: attn rows -> attn_s. warps 0..13, n = warp (+14) ----
    for (int nn = warp; nn < 16; nn += 14) {
        int bn = b * NN_ + q * 16 + nn;
        float pnr[8];
        #pragma unroll
        for (int k = 0; k < 8; k++) pnr[k] = g_pn[(size_t)bn * ATT_ + lane + 32 * k];

        float* arow = attn_s + nn * 52;
        if (!unif) {
            float v0 = -3.0e38f, v1 = -3.0e38f;
            int jj = 0;
            for (; jj + 1 < cnt; jj += 2) {
                const float* p0 = pl_s + jj * ATT_;
                const float* p1 = pl_s + (jj + 1) * ATT_;
                float s0 = 0.f, s1 = 0.f;
                #pragma unroll
                for (int k = 0; k < 8; k++) {
                    s0 += tanh_fast(pnr[k] + p0[lane + 32 * k]) * w2r[k];
                    s1 += tanh_fast(pnr[k] + p1[lane + 32 * k]) * w2r[k];
                }
                #pragma unroll
                for (int o = 16; o > 0; o >>= 1) {
                    s0 += __shfl_xor_sync(0xffffffffu, s0, o);
                    s1 += __shfl_xor_sync(0xffffffffu, s1, o);
                }
                if (jj < 32)      { if (lane == jj)      v0 = s0 + bias2; }
                else              { if (lane == jj - 32) v1 = s0 + bias2; }
                int j2 = jj + 1;
                if (j2 < 32)      { if (lane == j2)      v0 = s1 + bias2; }
                else              { if (lane == j2 - 32) v1 = s1 + bias2; }
            }
            if (jj < cnt) {
                const float* p0 = pl_s + jj * ATT_;
                float s0 = 0.f;
                #pragma unroll
                for (int k = 0; k < 8; k++)
                    s0 += tanh_fast(pnr[k] + p0[lane + 32 * k]) * w2r[k];
                #pragma unroll
                for (int o = 16; o > 0; o >>= 1)
                    s0 += __shfl_xor_sync(0xffffffffu, s0, o);
                if (jj < 32)      { if (lane == jj)      v0 = s0 + bias2; }
                else              { if (lane == jj - 32) v1 = s0 + bias2; }
            }
            float mx = fmaxf(v0, v1);
            #pragma unroll
            for (int o = 16; o > 0; o >>= 1)
                mx = fmaxf(mx, __shfl_xor_sync(0xffffffffu, mx, o));
            float e0 = __expf(v0 - mx), e1 = __expf(v1 - mx);
            float sv = e0 + e1;
            #pragma unroll
            for (int o = 16; o > 0; o >>= 1)
                sv += __shfl_xor_sync(0xffffffffu, sv, o);
            float inv = 1.f / sv;
            arow[lane] = (lane < cnt) ? e0 * inv : 0.f;
            if (lane < 20) arow[lane + 32] = (lane + 32 < cnt) ? e1 * inv : 0.f;
        } else {
            float u = 1.f / HL_;
            arow[lane] = (lane < cnt) ? u : 0.f;
            if (lane < 20) arow[lane + 32] = (lane + 32 < cnt) ? u : 0.f;
        }
    }
    __syncthreads();

    // ---- Phase C: lf gather (spill-free) + weighted sum ----
    int d = tid;   // 0..447
    float lf_reg[52];
    {
        const float* lv = log_vec + (size_t)b * HL_ * IN_ + d;
        const float* pe = pos_emb + POS_ + (d - IN_);
        bool lowd = (d < IN_);
        #pragma unroll
        for (int j = 0; j < 52; j++) {
            float v = 0.f;
            if (j < cnt) {
                int h = act_s[j];
                v = lowd ? lv[(size_t)h * IN_] : pe[(size_t)h * POS_];
            }
            lf_reg[j] = v;
        }
    }

    {
        const float4* at4 = (const float4*)attn_s;
        float* obase = out + ((size_t)(b * NN_ + q * 16)) * NEWS_ + d;
        #pragma unroll 4
        for (int i = 0; i < 16; i++) {
            float4 a4acc = make_float4(0.f, 0.f, 0.f, 0.f);
            #pragma unroll
            for (int k = 0; k < 13; k++) {
                float4 a4 = at4[i * 13 + k];
                a4acc.x += a4.x * lf_reg[4 * k];
                a4acc.y += a4.y * lf_reg[4 * k + 1];
                a4acc.z += a4.z * lf_reg[4 * k + 2];
                a4acc.w += a4.w * lf_reg[4 * k + 3];
            }
            obase[(size_t)i * NEWS_] = (a4acc.x + a4acc.y) + (a4acc.z + a4acc.w);
        }
    }

    // nf for this block's 16 rows
    {
        int rbase = b * NN_ + q * 16;
        bool lowd = (d < IN_);
        float posv = lowd ? 0.f : pos_emb[d - IN_];
        #pragma unroll 4
        for (int r = 0; r < 16; r++) {
            int gr = rbase + r;
            nf_out[(size_t)gr * NEWS_ + d] =
                lowd ? news_vec[(size_t)gr * IN_ + d] : posv;
        }
    }
}

// ---------------------------------------------------------------------------
extern "C" void kernel_launch(void* const* d_in, const int* in_sizes, int n_in,
                              void* d_out, int out_size)
{
    const float* log_vec  = (const float*)d_in[0];
    const int*   log_mask = (const int*)  d_in[1];
    const float* news_vec = (const float*)d_in[2];
    const float* pos_emb  = (const float*)d_in[3];
    const float* W1       = (const float*)d_in[4];
    const float* b1       = (const float*)d_in[5];
    const float* W2       = (const float*)d_in[6];
    const float* b2       = (const float*)d_in[7];
    float* out = (float*)d_out;

    const int NF_TOTAL = B_ * NN_ * NEWS_;
    cudaFuncSetAttribute(fused_kernel, cudaFuncAttributeMaxDynamicSharedMemorySize, FUSE_SMEM);

    cncl2_kernel<<<17, 256>>>(pos_emb, W1, b1, log_mask);
    gemm_mma_kernel<<<114, 256>>>(news_vec, log_vec, W1);
    fused_kernel<<<B_ * 4, 448, FUSE_SMEM>>>(log_vec, news_vec, pos_emb, W2, b2,
                                             out, out + NF_TOTAL);
}

// round 11
// speedup vs baseline: 1.6304x; 1.0900x over previous
#include <cuda_runtime.h>
#include <cuda_bf16.h>
#include <cstdint>

#define B_   64
#define NN_  64
#define HL_  50
#define IN_  384
#define POS_ 64
#define ATT_ 256
#define NEWS_ 448
#define W1COLS_ 896

// Scratch
__device__ float g_pn[B_ * NN_ * ATT_];
__device__ float g_pl[B_ * HL_ * ATT_];

__device__ __forceinline__ float tanh_fast(float x) {
    float y; asm("tanh.approx.f32 %0, %1;" : "=f"(y) : "f"(x)); return y;
}
__device__ __forceinline__ uint32_t to_tf32(float f) {
    uint32_t r; asm("cvt.rna.tf32.f32 %0, %1;" : "=r"(r) : "f"(f)); return r;
}
__device__ __forceinline__ void mma_tf32(float* c, const uint32_t* a, const uint32_t* b) {
    asm volatile(
        "mma.sync.aligned.m16n8k8.row.col.f32.tf32.tf32.f32 "
        "{%0,%1,%2,%3}, {%4,%5,%6,%7}, {%8,%9}, {%0,%1,%2,%3};"
        : "+f"(c[0]), "+f"(c[1]), "+f"(c[2]), "+f"(c[3])
        : "r"(a[0]), "r"(a[1]), "r"(a[2]), "r"(a[3]), "r"(b[0]), "r"(b[1]));
}

// ---------------------------------------------------------------------------
// Kernel B: mma.sync tf32 GEMM, FULL K=448 (pos tiles sourced from pos_emb).
//   mode 0: C[m,a] = [news_vec[m] | pos_emb[0]] . W1[a, 0:448]      + b1[a]
//   mode 1: C[m,a] = [log_vec[m] | pos_emb[1+m%50]] . W1[a, 448:896]
// Block tile 128x128, BK=32, NKT=14 (12 from A, 2 from pos_emb).
// ---------------------------------------------------------------------------
#define BK 32
#define LDT 36
#define NKT (NEWS_ / BK)   // 14

__global__ __launch_bounds__(256) void gemm_mma_kernel(
    const float* __restrict__ news_vec,
    const float* __restrict__ log_vec,
    const float* __restrict__ pos_emb,
    const float* __restrict__ b1,
    const float* __restrict__ W1)
{
    __shared__ uint32_t As[128 * LDT];
    __shared__ uint32_t Ws[128 * LDT];

    int tid  = threadIdx.x;
    int wid  = tid >> 5, lane = tid & 31;
    int gid  = lane >> 2, tig = lane & 3;
    int wm   = wid & 1;
    int wn   = wid >> 1;

    int bx   = blockIdx.x;
    int nh   = bx & 1;
    int tile = bx >> 1;
    int mode, mtile, w_off;
    const float* A;
    if (tile < 32) { mode = 0; mtile = tile;      A = news_vec; w_off = 0; }
    else           { mode = 1; mtile = tile - 32; A = log_vec;  w_off = NEWS_; }
    int n_base = nh * 128;

    int lrow = tid >> 3;           // 0..31
    int lf4  = tid & 7;            // 0..7
    const float* Abase = A  + (size_t)(mtile * 128 + lrow) * IN_ + lf4 * 4;
    const float* Wbase = W1 + (size_t)(n_base + lrow) * W1COLS_ + w_off + lf4 * 4;

    // pos-region source pointers (tiles 12,13): per page p
    const float* posA[4];
    #pragma unroll
    for (int p = 0; p < 4; p++) {
        if (mode == 0) {
            posA[p] = pos_emb + lf4 * 4;                       // row 0, broadcast
        } else {
            int r = mtile * 128 + p * 32 + lrow;
            posA[p] = pos_emb + (size_t)(1 + (r % HL_)) * POS_ + lf4 * 4;
        }
    }

    float acc[4][4][4];
    #pragma unroll
    for (int i = 0; i < 4; i++)
        #pragma unroll
        for (int j = 0; j < 4; j++)
            #pragma unroll
            for (int k = 0; k < 4; k++) acc[i][j][k] = 0.f;

    float4 aReg[4], wReg[4];
    #pragma unroll
    for (int p = 0; p < 4; p++) {
        aReg[p] = *(const float4*)(Abase + (size_t)p * 32 * IN_);
        wReg[p] = *(const float4*)(Wbase + (size_t)p * 32 * W1COLS_);
    }

    for (int kt = 0; kt < NKT; kt++) {
        #pragma unroll
        for (int p = 0; p < 4; p++) {
            uint32_t* as = &As[(p * 32 + lrow) * LDT + lf4 * 4];
            as[0] = to_tf32(aReg[p].x); as[1] = to_tf32(aReg[p].y);
            as[2] = to_tf32(aReg[p].z); as[3] = to_tf32(aReg[p].w);
            uint32_t* ws = &Ws[(p * 32 + lrow) * LDT + lf4 * 4];
            ws[0] = to_tf32(wReg[p].x); ws[1] = to_tf32(wReg[p].y);
            ws[2] = to_tf32(wReg[p].z); ws[3] = to_tf32(wReg[p].w);
        }
        __syncthreads();

        if (kt + 1 < NKT) {
            int t = kt + 1;
            if (t < IN_ / BK) {
                const float* An = Abase + t * BK;
                #pragma unroll
                for (int p = 0; p < 4; p++)
                    aReg[p] = *(const float4*)(An + (size_t)p * 32 * IN_);
            } else {
                int off = (t - IN_ / BK) * BK;
                #pragma unroll
                for (int p = 0; p < 4; p++)
                    aReg[p] = *(const float4*)(posA[p] + off);
            }
            const float* Wn = Wbase + t * BK;
            #pragma unroll
            for (int p = 0; p < 4; p++)
                wReg[p] = *(const float4*)(Wn + (size_t)p * 32 * W1COLS_);
        }

        #pragma unroll
        for (int kk = 0; kk < BK; kk += 8) {
            uint32_t afr[4][4], bfr[4][2];
            #pragma unroll
            for (int mf = 0; mf < 4; mf++) {
                int r0 = (wm * 64 + mf * 16 + gid) * LDT + kk + tig;
                afr[mf][0] = As[r0];
                afr[mf][1] = As[r0 + 8 * LDT];
                afr[mf][2] = As[r0 + 4];
                afr[mf][3] = As[r0 + 8 * LDT + 4];
            }
            #pragma unroll
            for (int nf = 0; nf < 4; nf++) {
                int c0 = (wn * 32 + nf * 8 + gid) * LDT + kk + tig;
                bfr[nf][0] = Ws[c0];
                bfr[nf][1] = Ws[c0 + 4];
            }
            #pragma unroll
            for (int mf = 0; mf < 4; mf++)
                #pragma unroll
                for (int nf = 0; nf < 4; nf++)
                    mma_tf32(acc[mf][nf], afr[mf], bfr[nf]);
        }
        __syncthreads();
    }

    float* outp = (mode == 0) ? g_pn : g_pl;
    #pragma unroll
    for (int mf = 0; mf < 4; mf++) {
        int r0 = mtile * 128 + wm * 64 + mf * 16 + gid;
        int r1 = r0 + 8;
        #pragma unroll
        for (int nf = 0; nf < 4; nf++) {
            int c = n_base + wn * 32 + nf * 8 + 2 * tig;
            float bx0 = 0.f, bx1 = 0.f;
            if (mode == 0) { bx0 = b1[c]; bx1 = b1[c + 1]; }
            float2 v0, v1;
            v0.x = acc[mf][nf][0] + bx0;
            v0.y = acc[mf][nf][1] + bx1;
            v1.x = acc[mf][nf][2] + bx0;
            v1.y = acc[mf][nf][3] + bx1;
            *(float2*)(outp + (size_t)r0 * ATT_ + c) = v0;
            *(float2*)(outp + (size_t)r1 * ATT_ + c) = v1;
        }
    }
}

// ---------------------------------------------------------------------------
// Kernel C: FUSED mask-compact + attn + out. Block = (b, quarter), 448 thr.
// ---------------------------------------------------------------------------
#define FUSE_SMEM ((50 * 256 + 16 * 52 + 64 + 4) * 4)
__global__ __launch_bounds__(448, 2) void fused_kernel(
    const float* __restrict__ log_vec,
    const float* __restrict__ news_vec,
    const float* __restrict__ pos_emb,
    const int*   __restrict__ log_mask,
    const float* __restrict__ W2,
    const float* __restrict__ b2,
    float* __restrict__ out,
    float* __restrict__ nf_out)
{
    extern __shared__ float sm[];
    float* pl_s   = sm;                        // 50*256
    float* attn_s = sm + 50 * 256;             // 16*52 (zero-padded)
    int*   act_s  = (int*)(sm + 50 * 256 + 16 * 52);   // 52 (padded 64)
    int*   meta_s = act_s + 64;                 // cnt, unif

    int tid  = threadIdx.x;
    int b    = blockIdx.x >> 2;
    int q    = blockIdx.x & 3;
    int warp = tid >> 5, lane = tid & 31;

    // mask compaction (warp 0, ballots)
    if (warp == 0) {
        int m1 = log_mask[b * HL_ + lane] != 0;
        int m2 = (lane < HL_ - 32) ? (log_mask[b * HL_ + 32 + lane] != 0) : 0;
        unsigned bb0 = __ballot_sync(0xffffffffu, m1);
        unsigned bb1 = __ballot_sync(0xffffffffu, m2);
        int cnt = __popc(bb0) + __popc(bb1);
        if (cnt == 0) {
            act_s[lane] = lane;
            if (lane < HL_ - 32) act_s[32 + lane] = 32 + lane;
            if (lane == 0) { meta_s[0] = HL_; meta_s[1] = 1; }
        } else {
            if (m1) act_s[__popc(bb0 & ((1u << lane) - 1u))] = lane;
            if (m2) act_s[__popc(bb0) + __popc(bb1 & ((1u << lane) - 1u))] = 32 + lane;
            if (lane == 0) { meta_s[0] = cnt; meta_s[1] = 0; }
        }
    }
    __syncthreads();
    int cnt  = meta_s[0];
    int unif = meta_s[1];

    // stage compact pl
    {
        int npl = cnt * 64;
        const float4* plg = (const float4*)(g_pl + (size_t)b * HL_ * ATT_);
        for (int i = tid; i < npl; i += 448) {
            int j = i >> 6, r = i & 63;
            ((float4*)pl_s)[j * 64 + r] = plg[(size_t)act_s[j] * 64 + r];
        }
    }
    float w2r[8];
    #pragma unroll
    for (int k = 0; k < 8; k++) w2r[k] = W2[lane + 32 * k];
    float bias2 = b2[0];
    __syncthreads();

    // ---- Phase B: attn rows -> attn_s. warps 0..13, n = warp (+14) ----
    for (int nn = warp; nn < 16; nn += 14) {
        int bn = b * NN_ + q * 16 + nn;
        float pnr[8];
        #pragma unroll
        for (int k = 0; k < 8; k++) pnr[k] = g_pn[(size_t)bn * ATT_ + lane + 32 * k];

        float* arow = attn_s + nn * 52;
        if (!unif) {
            float v0 = -3.0e38f, v1 = -3.0e38f;
            int jj = 0;
            for (; jj + 1 < cnt; jj += 2) {
                const float* p0 = pl_s + jj * ATT_;
                const float* p1 = pl_s + (jj + 1) * ATT_;
                float s0 = 0.f, s1 = 0.f;
                #pragma unroll
                for (int k = 0; k < 8; k++) {
                    s0 += tanh_fast(pnr[k] + p0[lane + 32 * k]) * w2r[k];
                    s1 += tanh_fast(pnr[k] + p1[lane + 32 * k]) * w2r[k];
                }
                #pragma unroll
                for (int o = 16; o > 0; o >>= 1) {
                    s0 += __shfl_xor_sync(0xffffffffu, s0, o);
                    s1 += __shfl_xor_sync(0xffffffffu, s1, o);
                }
                if (jj < 32)      { if (lane == jj)      v0 = s0 + bias2; }
                else              { if (lane == jj - 32) v1 = s0 + bias2; }
                int j2 = jj + 1;
                if (j2 < 32)      { if (lane == j2)      v0 = s1 + bias2; }
                else              { if (lane == j2 - 32) v1 = s1 + bias2; }
            }
            if (jj < cnt) {
                const float* p0 = pl_s + jj * ATT_;
                float s0 = 0.f;
                #pragma unroll
                for (int k = 0; k < 8; k++)
                    s0 += tanh_fast(pnr[k] + p0[lane + 32 * k]) * w2r[k];
                #pragma unroll
                for (int o = 16; o > 0; o >>= 1)
                    s0 += __shfl_xor_sync(0xffffffffu, s0, o);
                if (jj < 32)      { if (lane == jj)      v0 = s0 + bias2; }
                else              { if (lane == jj - 32) v1 = s0 + bias2; }
            }
            float mx = fmaxf(v0, v1);
            #pragma unroll
            for (int o = 16; o > 0; o >>= 1)
                mx = fmaxf(mx, __shfl_xor_sync(0xffffffffu, mx, o));
            float e0 = __expf(v0 - mx), e1 = __expf(v1 - mx);
            float sv = e0 + e1;
            #pragma unroll
            for (int o = 16; o > 0; o >>= 1)
                sv += __shfl_xor_sync(0xffffffffu, sv, o);
            float inv = 1.f / sv;
            arow[lane] = (lane < cnt) ? e0 * inv : 0.f;
            if (lane < 20) arow[lane + 32] = (lane + 32 < cnt) ? e1 * inv : 0.f;
        } else {
            float u = 1.f / HL_;
            arow[lane] = (lane < cnt) ? u : 0.f;
            if (lane < 20) arow[lane + 32] = (lane + 32 < cnt) ? u : 0.f;
        }
    }
    __syncthreads();

    // ---- Phase C: lf gather (spill-free) + weighted sum ----
    int d = tid;   // 0..447
    float lf_reg[52];
    {
        const float* lv = log_vec + (size_t)b * HL_ * IN_ + d;
        const float* pe = pos_emb + POS_ + (d - IN_);
        bool lowd = (d < IN_);
        #pragma unroll
        for (int j = 0; j < 52; j++) {
            float v = 0.f;
            if (j < cnt) {
                int h = act_s[j];
                v = lowd ? lv[(size_t)h * IN_] : pe[(size_t)h * POS_];
            }
            lf_reg[j] = v;
        }
    }

    {
        const float4* at4 = (const float4*)attn_s;
        float* obase = out + ((size_t)(b * NN_ + q * 16)) * NEWS_ + d;
        #pragma unroll 4
        for (int i = 0; i < 16; i++) {
            float4 a4acc = make_float4(0.f, 0.f, 0.f, 0.f);
            #pragma unroll
            for (int k = 0; k < 13; k++) {
                float4 a4 = at4[i * 13 + k];
                a4acc.x += a4.x * lf_reg[4 * k];
                a4acc.y += a4.y * lf_reg[4 * k + 1];
                a4acc.z += a4.z * lf_reg[4 * k + 2];
                a4acc.w += a4.w * lf_reg[4 * k + 3];
            }
            obase[(size_t)i * NEWS_] = (a4acc.x + a4acc.y) + (a4acc.z + a4acc.w);
        }
    }

    // nf for this block's 16 rows
    {
        int rbase = b * NN_ + q * 16;
        bool lowd = (d < IN_);
        float posv = lowd ? 0.f : pos_emb[d - IN_];
        #pragma unroll 4
        for (int r = 0; r < 16; r++) {
            int gr = rbase + r;
            nf_out[(size_t)gr * NEWS_ + d] =
                lowd ? news_vec[(size_t)gr * IN_ + d] : posv;
        }
    }
}

// ---------------------------------------------------------------------------
extern "C" void kernel_launch(void* const* d_in, const int* in_sizes, int n_in,
                              void* d_out, int out_size)
{
    const float* log_vec  = (const float*)d_in[0];
    const int*   log_mask = (const int*)  d_in[1];
    const float* news_vec = (const float*)d_in[2];
    const float* pos_emb  = (const float*)d_in[3];
    const float* W1       = (const float*)d_in[4];
    const float* b1       = (const float*)d_in[5];
    const float* W2       = (const float*)d_in[6];
    const float* b2       = (const float*)d_in[7];
    float* out = (float*)d_out;

    const int NF_TOTAL = B_ * NN_ * NEWS_;
    cudaFuncSetAttribute(fused_kernel, cudaFuncAttributeMaxDynamicSharedMemorySize, FUSE_SMEM);

    gemm_mma_kernel<<<114, 256>>>(news_vec, log_vec, pos_emb, b1, W1);
    fused_kernel<<<B_ * 4, 448, FUSE_SMEM>>>(log_vec, news_vec, pos_emb, log_mask,
                                             W2, b2, out, out + NF_TOTAL);
}